// round 1
// baseline (speedup 1.0000x reference)
#include <cuda_runtime.h>
#include <mma.h>
#include <cstdint>
#include <cstdio>

using namespace nvcuda;

// Problem dims (fixed by setup_inputs)
#define B_SZ    2
#define S_LEN   2048
#define D_DIM   2048
#define H_DIM   2048
#define F_DIM   6144
#define KCONV   4
#define TOKENS  (B_SZ * S_LEN)   // 4096

// ---------------------------------------------------------------------------
// Scratch: one big __device__ array (no cudaMalloc allowed).
// Layout (floats):
//   xn   [TOKENS*D]    left [TOKENS*H]    rp   [TOKENS*H]   conv [TOKENS*H]
//   rg   [TOKENS*H]    ig   [TOKENS*H]    x1   [TOKENS*D]   x1n  [TOKENS*D]
//   f1   [TOKENS*F]    f2   [TOKENS*F]
// ---------------------------------------------------------------------------
#define TD ((size_t)TOKENS * D_DIM)      // 8,388,608
#define TF ((size_t)TOKENS * F_DIM)      // 25,165,824
#define SCRATCH_FLOATS (8 * TD + 2 * TF) // ~470 MB
__device__ float g_scratch[SCRATCH_FLOATS];

// ---------------------------------------------------------------------------
// Helpers
// ---------------------------------------------------------------------------
__device__ __forceinline__ float gelu_f(float x) {
    // exact gelu: 0.5 * x * (1 + erf(x / sqrt(2)))
    return 0.5f * x * (1.0f + erff(x * 0.70710678118654752440f));
}

// ---------------------------------------------------------------------------
// RMSNorm: one block per row of length D (2048). out = w * x / rms
// ---------------------------------------------------------------------------
__global__ void rmsnorm_kernel(const float* __restrict__ x,
                               const float* __restrict__ w,
                               float* __restrict__ out, int D) {
    const float* row = x + (size_t)blockIdx.x * D;
    float* orow = out + (size_t)blockIdx.x * D;

    float s = 0.0f;
    for (int i = threadIdx.x; i < D; i += blockDim.x) {
        float v = row[i];
        s += v * v;
    }
    // warp reduce
    #pragma unroll
    for (int off = 16; off > 0; off >>= 1)
        s += __shfl_xor_sync(0xFFFFFFFF, s, off);

    __shared__ float red[32];
    int lane = threadIdx.x & 31;
    int warp = threadIdx.x >> 5;
    if (lane == 0) red[warp] = s;
    __syncthreads();
    int nwarps = blockDim.x >> 5;
    if (warp == 0) {
        float t = (lane < nwarps) ? red[lane] : 0.0f;
        #pragma unroll
        for (int off = 16; off > 0; off >>= 1)
            t += __shfl_xor_sync(0xFFFFFFFF, t, off);
        if (lane == 0) red[0] = t;
    }
    __syncthreads();
    float total = red[0];
    float inv = rsqrtf(total / (float)D + 1e-8f);

    for (int i = threadIdx.x; i < D; i += blockDim.x)
        orow[i] = w[i] * row[i] * inv;
}

// ---------------------------------------------------------------------------
// TF32 WMMA GEMM: C[M,N] = A[M,K] @ B[K,N]  (raw accumulators, no epilogue)
// Block tile 128x128x32, 256 threads = 8 warps (2x4), warp tile 64x32 (4x2 frags)
// ---------------------------------------------------------------------------
#define BM 128
#define BN 128
#define BK 32
#define LDA_S 36   // BK + 4 pad (multiple of 4)
#define LDB_S 132  // BN + 4 pad (multiple of 4)

__global__ void __launch_bounds__(256)
gemm_tf32_kernel(const float* __restrict__ A, const float* __restrict__ B,
                 float* __restrict__ C, int M, int N, int K) {
    __shared__ float As[BM * LDA_S];
    __shared__ float Bs[BK * LDB_S];

    const int bm = blockIdx.y * BM;
    const int bn = blockIdx.x * BN;
    const int tid = threadIdx.x;
    const int warp = tid >> 5;
    const int wm = (warp >> 2) * 64;   // 2 warp-rows
    const int wn = (warp & 3) * 32;    // 4 warp-cols

    wmma::fragment<wmma::accumulator, 16, 16, 8, float> acc[4][2];
    #pragma unroll
    for (int mi = 0; mi < 4; mi++)
        #pragma unroll
        for (int ni = 0; ni < 2; ni++)
            wmma::fill_fragment(acc[mi][ni], 0.0f);

    // A tile loads: 128 rows x 32 cols, 2 threads per row, 16 floats each
    const int arow = tid >> 1;
    const int acol = (tid & 1) * 16;
    // B tile loads: 32 rows x 128 cols, 8 threads per row, 16 floats each
    const int brow = tid >> 3;
    const int bcol = (tid & 7) * 16;

    const float* Aptr = A + (size_t)(bm + arow) * K + acol;
    const float* Bptr = B + (size_t)brow * N + (bn + bcol);

    for (int k0 = 0; k0 < K; k0 += BK) {
        // stage A (convert to tf32)
        float* asd = &As[arow * LDA_S + acol];
        #pragma unroll
        for (int v = 0; v < 4; v++) {
            float4 t = *(const float4*)(Aptr + v * 4);
            asd[v * 4 + 0] = wmma::__float_to_tf32(t.x);
            asd[v * 4 + 1] = wmma::__float_to_tf32(t.y);
            asd[v * 4 + 2] = wmma::__float_to_tf32(t.z);
            asd[v * 4 + 3] = wmma::__float_to_tf32(t.w);
        }
        // stage B
        float* bsd = &Bs[brow * LDB_S + bcol];
        #pragma unroll
        for (int v = 0; v < 4; v++) {
            float4 t = *(const float4*)(Bptr + v * 4);
            bsd[v * 4 + 0] = wmma::__float_to_tf32(t.x);
            bsd[v * 4 + 1] = wmma::__float_to_tf32(t.y);
            bsd[v * 4 + 2] = wmma::__float_to_tf32(t.z);
            bsd[v * 4 + 3] = wmma::__float_to_tf32(t.w);
        }
        Aptr += BK;
        Bptr += (size_t)BK * N;
        __syncthreads();

        #pragma unroll
        for (int kk = 0; kk < BK; kk += 8) {
            wmma::fragment<wmma::matrix_a, 16, 16, 8, wmma::precision::tf32,
                           wmma::row_major> af[4];
            wmma::fragment<wmma::matrix_b, 16, 16, 8, wmma::precision::tf32,
                           wmma::row_major> bf[2];
            #pragma unroll
            for (int mi = 0; mi < 4; mi++)
                wmma::load_matrix_sync(af[mi], &As[(wm + mi * 16) * LDA_S + kk], LDA_S);
            #pragma unroll
            for (int ni = 0; ni < 2; ni++)
                wmma::load_matrix_sync(bf[ni], &Bs[kk * LDB_S + wn + ni * 16], LDB_S);
            #pragma unroll
            for (int mi = 0; mi < 4; mi++)
                #pragma unroll
                for (int ni = 0; ni < 2; ni++)
                    wmma::mma_sync(acc[mi][ni], af[mi], bf[ni], acc[mi][ni]);
        }
        __syncthreads();
    }

    #pragma unroll
    for (int mi = 0; mi < 4; mi++)
        #pragma unroll
        for (int ni = 0; ni < 2; ni++)
            wmma::store_matrix_sync(
                C + (size_t)(bm + wm + mi * 16) * N + (bn + wn + ni * 16),
                acc[mi][ni], N, wmma::mem_row_major);
}

// ---------------------------------------------------------------------------
// Epilogue: C = act(C + bias[col] (+ res))  in place.  ACT: 0 none, 1 gelu, 2 sigmoid
// ---------------------------------------------------------------------------
template <int ACT, bool RES>
__global__ void epilogue_kernel(float* __restrict__ C,
                                const float* __restrict__ bias,
                                const float* __restrict__ res,
                                size_t total, size_t N) {
    for (size_t i = (size_t)blockIdx.x * blockDim.x + threadIdx.x; i < total;
         i += (size_t)gridDim.x * blockDim.x) {
        float v = C[i] + bias[i % N];
        if (RES) v += res[i];
        if (ACT == 1) v = gelu_f(v);
        if (ACT == 2) v = 1.0f / (1.0f + expf(-v));
        C[i] = v;
    }
}

// ---------------------------------------------------------------------------
// Causal depthwise conv, K=4: y[b,t,h] = sum_k w[k,h]*x[b,t-3+k,h] + b[h]
// ---------------------------------------------------------------------------
__global__ void conv_kernel(const float* __restrict__ x,
                            const float* __restrict__ w,
                            const float* __restrict__ bias,
                            float* __restrict__ y) {
    const size_t total = (size_t)TOKENS * H_DIM;
    for (size_t i = (size_t)blockIdx.x * blockDim.x + threadIdx.x; i < total;
         i += (size_t)gridDim.x * blockDim.x) {
        int h = (int)(i % H_DIM);
        int t = (int)((i / H_DIM) % S_LEN);
        float acc = bias[h];
        #pragma unroll
        for (int k = 0; k < KCONV; k++) {
            int tt = t - (KCONV - 1) + k;
            if (tt >= 0)
                acc += w[k * H_DIM + h] * x[i + (size_t)(tt - t) * H_DIM];
        }
        y[i] = acc;
    }
}

// ---------------------------------------------------------------------------
// RG-LRU gate math: given r=sigmoid(.), i=sigmoid(.), xc (conv out), a_param:
//   log_a = -8 * softplus(a_param[h]) * r ;  a = exp(log_a)
//   b = sqrt(-expm1(2*log_a)) * i * xc
// Writes a over r-buffer, b over i-buffer.
// ---------------------------------------------------------------------------
__global__ void ab_kernel(float* __restrict__ rbuf, float* __restrict__ ibuf,
                          const float* __restrict__ xc,
                          const float* __restrict__ ap) {
    const size_t total = (size_t)TOKENS * H_DIM;
    for (size_t i = (size_t)blockIdx.x * blockDim.x + threadIdx.x; i < total;
         i += (size_t)gridDim.x * blockDim.x) {
        int h = (int)(i % H_DIM);
        float sp = log1pf(expf(ap[h]));     // a_param in [0.5,3] -> safe
        float la = -8.0f * sp * rbuf[i];
        float a = expf(la);
        float mult = sqrtf(-expm1f(2.0f * la));
        float b = mult * ibuf[i] * xc[i];
        rbuf[i] = a;
        ibuf[i] = b;
    }
}

// ---------------------------------------------------------------------------
// Sequential scan per (batch, channel): h_t = a_t*h_{t-1} + b_t
// 4096 independent chains; coalesced across h.
// ---------------------------------------------------------------------------
__global__ void scan_kernel(const float* __restrict__ a,
                            const float* __restrict__ b,
                            float* __restrict__ hout) {
    int idx = blockIdx.x * blockDim.x + threadIdx.x;
    if (idx >= B_SZ * H_DIM) return;
    int bb = idx / H_DIM;
    int hh = idx % H_DIM;
    size_t base = (size_t)bb * S_LEN * H_DIM + hh;
    float state = 0.0f;
    #pragma unroll 4
    for (int t = 0; t < S_LEN; t++) {
        size_t o = base + (size_t)t * H_DIM;
        state = fmaf(a[o], state, b[o]);
        hout[o] = state;
    }
}

// ---------------------------------------------------------------------------
// Elementwise multiply: c = a * b
// ---------------------------------------------------------------------------
__global__ void mult_kernel(const float* __restrict__ a,
                            const float* __restrict__ b,
                            float* __restrict__ c, size_t total) {
    for (size_t i = (size_t)blockIdx.x * blockDim.x + threadIdx.x; i < total;
         i += (size_t)gridDim.x * blockDim.x)
        c[i] = a[i] * b[i];
}

// ---------------------------------------------------------------------------
// Host launch
// ---------------------------------------------------------------------------
static inline void launch_gemm(const float* A, const float* B, float* C,
                               int M, int N, int K) {
    dim3 grid(N / BN, M / BM);
    gemm_tf32_kernel<<<grid, 256>>>(A, B, C, M, N, K);
}

extern "C" void kernel_launch(void* const* d_in, const int* in_sizes, int n_in,
                              void* d_out, int out_size) {
    (void)in_sizes; (void)n_in; (void)out_size;
    const float* x       = (const float*)d_in[0];
    const float* norm1_w = (const float*)d_in[1];
    const float* left_W  = (const float*)d_in[2];
    const float* left_b  = (const float*)d_in[3];
    const float* right_W = (const float*)d_in[4];
    const float* right_b = (const float*)d_in[5];
    const float* conv_w  = (const float*)d_in[6];
    const float* conv_b  = (const float*)d_in[7];
    const float* ga_W    = (const float*)d_in[8];
    const float* ga_b    = (const float*)d_in[9];
    const float* gx_W    = (const float*)d_in[10];
    const float* gx_b    = (const float*)d_in[11];
    const float* a_param = (const float*)d_in[12];
    const float* out_W   = (const float*)d_in[13];
    const float* out_b   = (const float*)d_in[14];
    const float* norm2_w = (const float*)d_in[15];
    const float* up1_W   = (const float*)d_in[16];
    const float* up1_b   = (const float*)d_in[17];
    const float* up2_W   = (const float*)d_in[18];
    const float* up2_b   = (const float*)d_in[19];
    const float* down_W  = (const float*)d_in[20];
    const float* down_b  = (const float*)d_in[21];
    float* out = (float*)d_out;

    float* scratch = nullptr;
    cudaGetSymbolAddress((void**)&scratch, g_scratch);
    float* xn   = scratch;
    float* left = xn + TD;
    float* rp   = left + TD;    // right pre-activation / later reused for scan output
    float* cv   = rp + TD;      // conv output
    float* rg   = cv + TD;      // r gate -> a
    float* ig   = rg + TD;      // i gate -> b
    float* x1   = ig + TD;
    float* x1n  = x1 + TD;
    float* f1   = x1n + TD;
    float* f2   = f1 + TF;

    const int EPI_BLOCKS = 4096;

    // ---- recurrent sub-block ----
    rmsnorm_kernel<<<TOKENS, 256>>>(x, norm1_w, xn, D_DIM);

    launch_gemm(xn, left_W, left, TOKENS, H_DIM, D_DIM);
    epilogue_kernel<1, false><<<EPI_BLOCKS, 256>>>(left, left_b, nullptr, TD, H_DIM);

    launch_gemm(xn, right_W, rp, TOKENS, H_DIM, D_DIM);
    epilogue_kernel<0, false><<<EPI_BLOCKS, 256>>>(rp, right_b, nullptr, TD, H_DIM);

    conv_kernel<<<EPI_BLOCKS, 256>>>(rp, conv_w, conv_b, cv);

    launch_gemm(cv, ga_W, rg, TOKENS, H_DIM, H_DIM);
    epilogue_kernel<2, false><<<EPI_BLOCKS, 256>>>(rg, ga_b, nullptr, TD, H_DIM);

    launch_gemm(cv, gx_W, ig, TOKENS, H_DIM, H_DIM);
    epilogue_kernel<2, false><<<EPI_BLOCKS, 256>>>(ig, gx_b, nullptr, TD, H_DIM);

    ab_kernel<<<EPI_BLOCKS, 256>>>(rg, ig, cv, a_param);

    scan_kernel<<<32, 128>>>(rg, ig, rp);   // h written into rp

    mult_kernel<<<EPI_BLOCKS, 256>>>(left, rp, left, TD);

    launch_gemm(left, out_W, x1, TOKENS, D_DIM, H_DIM);
    epilogue_kernel<0, true><<<EPI_BLOCKS, 256>>>(x1, out_b, x, TD, D_DIM);

    // ---- gated MLP sub-block ----
    rmsnorm_kernel<<<TOKENS, 256>>>(x1, norm2_w, x1n, D_DIM);

    launch_gemm(x1n, up1_W, f1, TOKENS, F_DIM, D_DIM);
    epilogue_kernel<1, false><<<EPI_BLOCKS, 256>>>(f1, up1_b, nullptr, TF, F_DIM);

    launch_gemm(x1n, up2_W, f2, TOKENS, F_DIM, D_DIM);
    epilogue_kernel<0, false><<<EPI_BLOCKS, 256>>>(f2, up2_b, nullptr, TF, F_DIM);

    mult_kernel<<<EPI_BLOCKS, 256>>>(f1, f2, f1, TF);

    launch_gemm(f1, down_W, out, TOKENS, D_DIM, F_DIM);
    epilogue_kernel<0, true><<<EPI_BLOCKS, 256>>>(out, down_b, x1, TD, D_DIM);
}

// round 4
// speedup vs baseline: 1.2963x; 1.2963x over previous
#include <cuda_runtime.h>
#include <mma.h>
#include <cstdint>

using namespace nvcuda;

// ============================================================================
// Problem dims (fixed by setup_inputs)
// ============================================================================
#define B_SZ    2
#define S_LEN   2048
#define D_DIM   2048
#define H_DIM   2048
#define F_DIM   6144
#define KCONV   4
#define TOKENS  (B_SZ * S_LEN)   // 4096

#define TD ((size_t)TOKENS * D_DIM)      // 8,388,608
#define TF ((size_t)TOKENS * F_DIM)      // 25,165,824
#define SCRATCH_FLOATS (8 * TD + 2 * TF)
__device__ float g_scratch[SCRATCH_FLOATS];

// ============================================================================
// GEMM: C[M,N] = A[M,K] @ B[K,N], tf32 WMMA + cp.async 3-stage pipeline.
// Block tile 256x128x32, 512 threads (16 warps), warp tile 64x32.
// Fused epilogue: bias + activation (+ residual).
// ============================================================================
#define BM 256
#define BN 128
#define BK 32
#define STAGES 3
#define LDA_S 36     // BK + 4 pad (floats)
#define LDB_S 132    // BN + 4 pad
#define LDC_S 132
#define A_ST (BM * LDA_S)                    // 9216 floats
#define B_ST (BK * LDB_S)                    // 4224 floats
#define STAGE_FLOATS (A_ST + B_ST)           // 13440
#define GEMM_SMEM (STAGES * STAGE_FLOATS * 4)   // 161,280 B

__device__ __forceinline__ void cp_async16(uint32_t sdst, const float* gsrc) {
    asm volatile("cp.async.cg.shared.global [%0], [%1], 16;"
                 :: "r"(sdst), "l"(gsrc) : "memory");
}
__device__ __forceinline__ void cp_commit() {
    asm volatile("cp.async.commit_group;" ::: "memory");
}
template <int N>
__device__ __forceinline__ void cp_wait() {
    asm volatile("cp.async.wait_group %0;" :: "n"(N) : "memory");
}

__device__ __forceinline__ float gelu_f(float x) {
    return 0.5f * x * (1.0f + erff(x * 0.70710678118654752440f));
}
__device__ __forceinline__ float sigmoid_f(float x) {
    return 1.0f / (1.0f + expf(-x));
}

// ACT codes: 0 none, 1 gelu, 2 sigmoid
template <int ACT0, int ACT1, bool RES>
__global__ void __launch_bounds__(512, 1)
gemm_kernel(const float* __restrict__ A, const float* __restrict__ B,
            float* __restrict__ C0, int ldc0, const float* __restrict__ bias0,
            float* __restrict__ C1, int ldc1, const float* __restrict__ bias1,
            const float* __restrict__ res,
            int M, int N, int K, int Nsplit) {
    extern __shared__ float smemf[];
    const int tid = threadIdx.x;
    const int warp = tid >> 5;
    const int bm = blockIdx.y * BM;
    const int bn = blockIdx.x * BN;

    const int wm = (warp >> 2) * 64;   // 4 warp rows of 64
    const int wn = (warp & 3) * 32;    // 4 warp cols of 32

    wmma::fragment<wmma::accumulator, 16, 16, 8, float> acc[4][2];
    #pragma unroll
    for (int mi = 0; mi < 4; mi++)
        #pragma unroll
        for (int ni = 0; ni < 2; ni++)
            wmma::fill_fragment(acc[mi][ni], 0.0f);

    const uint32_t smem_u32 = (uint32_t)__cvta_generic_to_shared(smemf);
    const int nk = K / BK;

    auto issue_stage = [&](int s, int kc) {
        const uint32_t sA = smem_u32 + (uint32_t)(s * STAGE_FLOATS) * 4u;
        const uint32_t sB = sA + (uint32_t)A_ST * 4u;
        const float* Ab = A + (size_t)bm * K + (size_t)kc * BK;
        const float* Bb = B + (size_t)kc * BK * N + bn;
        #pragma unroll
        for (int p = 0; p < 4; p++) {       // A: 256 rows x 8 chunks(16B)
            int id = p * 512 + tid;
            int r = id >> 3, c = id & 7;
            cp_async16(sA + (uint32_t)(r * LDA_S + c * 4) * 4u,
                       Ab + (size_t)r * K + c * 4);
        }
        #pragma unroll
        for (int p = 0; p < 2; p++) {       // B: 32 rows x 32 chunks
            int id = p * 512 + tid;
            int r = id >> 5, c = id & 31;
            cp_async16(sB + (uint32_t)(r * LDB_S + c * 4) * 4u,
                       Bb + (size_t)r * N + c * 4);
        }
    };

    // prologue: prefetch STAGES-1 stages
    #pragma unroll
    for (int s = 0; s < STAGES - 1; s++) {
        issue_stage(s, s);
        cp_commit();
    }

    int cur = 0;
    for (int kc = 0; kc < nk; kc++) {
        cp_wait<STAGES - 2>();
        __syncthreads();

        int pf = kc + STAGES - 1;
        if (pf < nk) {
            int s = cur + STAGES - 1;
            if (s >= STAGES) s -= STAGES;
            issue_stage(s, pf);
        }
        cp_commit();

        const float* sA = smemf + cur * STAGE_FLOATS;
        const float* sB = sA + A_ST;
        #pragma unroll
        for (int kk = 0; kk < BK; kk += 8) {
            wmma::fragment<wmma::matrix_a, 16, 16, 8, wmma::precision::tf32,
                           wmma::row_major> af[4];
            wmma::fragment<wmma::matrix_b, 16, 16, 8, wmma::precision::tf32,
                           wmma::row_major> bf[2];
            #pragma unroll
            for (int mi = 0; mi < 4; mi++) {
                wmma::load_matrix_sync(af[mi], sA + (wm + mi * 16) * LDA_S + kk,
                                       LDA_S);
                #pragma unroll
                for (int e = 0; e < af[mi].num_elements; e++)
                    af[mi].x[e] = wmma::__float_to_tf32(af[mi].x[e]);
            }
            #pragma unroll
            for (int ni = 0; ni < 2; ni++) {
                wmma::load_matrix_sync(bf[ni], sB + kk * LDB_S + wn + ni * 16,
                                       LDB_S);
                #pragma unroll
                for (int e = 0; e < bf[ni].num_elements; e++)
                    bf[ni].x[e] = wmma::__float_to_tf32(bf[ni].x[e]);
            }
            #pragma unroll
            for (int mi = 0; mi < 4; mi++)
                #pragma unroll
                for (int ni = 0; ni < 2; ni++)
                    wmma::mma_sync(acc[mi][ni], af[mi], bf[ni], acc[mi][ni]);
        }
        cur = (cur + 1 == STAGES) ? 0 : cur + 1;
    }

    // ---- fused epilogue via smem ----
    cp_wait<0>();
    __syncthreads();
    float* Cs = smemf;   // 256 x 132 floats = 135,168 B <= GEMM_SMEM
    #pragma unroll
    for (int mi = 0; mi < 4; mi++)
        #pragma unroll
        for (int ni = 0; ni < 2; ni++)
            wmma::store_matrix_sync(Cs + (wm + mi * 16) * LDC_S + wn + ni * 16,
                                    acc[mi][ni], LDC_S, wmma::mem_row_major);
    __syncthreads();

    const bool half1 = (bn >= Nsplit);
    float* Cout = half1 ? C1 : C0;
    const int ldc = half1 ? ldc1 : ldc0;
    const float* bias = half1 ? bias1 : bias0;
    const int act = half1 ? ACT1 : ACT0;
    const int colbase = bn - (half1 ? Nsplit : 0);

    // 512 threads: 2 per row, 64 cols each (16 float4)
    const int r = tid >> 1;
    const int cseg = (tid & 1) * 64;
    const size_t grow = (size_t)(bm + r);
    float* gout = Cout + grow * ldc + colbase + cseg;
    const float* biasp = bias + colbase + cseg;
    const float* resp = RES ? (res + grow * ldc0 + colbase + cseg) : nullptr;
    const float* csrow = Cs + r * LDC_S + cseg;

    #pragma unroll
    for (int j = 0; j < 16; j++) {
        float4 v = *(const float4*)(csrow + j * 4);
        float4 b = *(const float4*)(biasp + j * 4);
        v.x += b.x; v.y += b.y; v.z += b.z; v.w += b.w;
        if (act == 1) {
            v.x = gelu_f(v.x); v.y = gelu_f(v.y);
            v.z = gelu_f(v.z); v.w = gelu_f(v.w);
        } else if (act == 2) {
            v.x = sigmoid_f(v.x); v.y = sigmoid_f(v.y);
            v.z = sigmoid_f(v.z); v.w = sigmoid_f(v.w);
        }
        if (RES) {
            float4 rv = *(const float4*)(resp + j * 4);
            v.x += rv.x; v.y += rv.y; v.z += rv.z; v.w += rv.w;
        }
        *(float4*)(gout + j * 4) = v;
    }
}

// ============================================================================
// Elementwise kernels
// ============================================================================
__global__ void rmsnorm_kernel(const float* __restrict__ x,
                               const float* __restrict__ w,
                               float* __restrict__ out, int D) {
    const float* row = x + (size_t)blockIdx.x * D;
    float* orow = out + (size_t)blockIdx.x * D;
    float s = 0.0f;
    for (int i = threadIdx.x; i < D; i += blockDim.x) {
        float v = row[i];
        s += v * v;
    }
    #pragma unroll
    for (int off = 16; off > 0; off >>= 1)
        s += __shfl_xor_sync(0xFFFFFFFF, s, off);
    __shared__ float red[32];
    int lane = threadIdx.x & 31, warp = threadIdx.x >> 5;
    if (lane == 0) red[warp] = s;
    __syncthreads();
    int nwarps = blockDim.x >> 5;
    if (warp == 0) {
        float t = (lane < nwarps) ? red[lane] : 0.0f;
        #pragma unroll
        for (int off = 16; off > 0; off >>= 1)
            t += __shfl_xor_sync(0xFFFFFFFF, t, off);
        if (lane == 0) red[0] = t;
    }
    __syncthreads();
    float inv = rsqrtf(red[0] / (float)D + 1e-8f);
    for (int i = threadIdx.x; i < D; i += blockDim.x)
        orow[i] = w[i] * row[i] * inv;
}

__global__ void conv_kernel(const float* __restrict__ x,
                            const float* __restrict__ w,
                            const float* __restrict__ bias,
                            float* __restrict__ y) {
    const size_t total = (size_t)TOKENS * H_DIM;
    for (size_t i = (size_t)blockIdx.x * blockDim.x + threadIdx.x; i < total;
         i += (size_t)gridDim.x * blockDim.x) {
        int h = (int)(i % H_DIM);
        int t = (int)((i / H_DIM) % S_LEN);
        float acc = bias[h];
        #pragma unroll
        for (int k = 0; k < KCONV; k++) {
            int tt = t - (KCONV - 1) + k;
            if (tt >= 0)
                acc += w[k * H_DIM + h] * x[i + (size_t)(tt - t) * H_DIM];
        }
        y[i] = acc;
    }
}

// r,i already sigmoided (fused in GEMM). Compute a, b in place.
__global__ void ab_kernel(float* __restrict__ rbuf, float* __restrict__ ibuf,
                          const float* __restrict__ xc,
                          const float* __restrict__ ap) {
    const size_t total = (size_t)TOKENS * H_DIM;
    for (size_t i = (size_t)blockIdx.x * blockDim.x + threadIdx.x; i < total;
         i += (size_t)gridDim.x * blockDim.x) {
        int h = (int)(i % H_DIM);
        float sp = log1pf(expf(ap[h]));
        float la = -8.0f * sp * rbuf[i];
        float a = expf(la);
        float mult = sqrtf(-expm1f(2.0f * la));
        rbuf[i] = a;
        ibuf[i] = mult * ibuf[i] * xc[i];
    }
}

__global__ void scan_kernel(const float* __restrict__ a,
                            const float* __restrict__ b,
                            float* __restrict__ hout) {
    int idx = blockIdx.x * blockDim.x + threadIdx.x;
    if (idx >= B_SZ * H_DIM) return;
    int bb = idx / H_DIM;
    int hh = idx % H_DIM;
    size_t base = (size_t)bb * S_LEN * H_DIM + hh;
    float state = 0.0f;
    #pragma unroll 4
    for (int t = 0; t < S_LEN; t++) {
        size_t o = base + (size_t)t * H_DIM;
        state = fmaf(a[o], state, b[o]);
        hout[o] = state;
    }
}

__global__ void mult_kernel(const float* __restrict__ a,
                            const float* __restrict__ b,
                            float* __restrict__ c, size_t total) {
    for (size_t i = (size_t)blockIdx.x * blockDim.x + threadIdx.x; i < total;
         i += (size_t)gridDim.x * blockDim.x)
        c[i] = a[i] * b[i];
}

// ============================================================================
// Host launch
// ============================================================================
template <int ACT0, int ACT1, bool RES>
static inline void launch_gemm(const float* A, const float* B,
                               float* C0, int ldc0, const float* bias0,
                               float* C1, int ldc1, const float* bias1,
                               const float* res,
                               int M, int N, int K, int Nsplit) {
    dim3 grid(N / BN, M / BM);
    gemm_kernel<ACT0, ACT1, RES><<<grid, 512, GEMM_SMEM>>>(
        A, B, C0, ldc0, bias0, C1, ldc1, bias1, res, M, N, K, Nsplit);
}

extern "C" void kernel_launch(void* const* d_in, const int* in_sizes, int n_in,
                              void* d_out, int out_size) {
    (void)in_sizes; (void)n_in; (void)out_size;
    const float* x       = (const float*)d_in[0];
    const float* norm1_w = (const float*)d_in[1];
    const float* left_W  = (const float*)d_in[2];
    const float* left_b  = (const float*)d_in[3];
    const float* right_W = (const float*)d_in[4];
    const float* right_b = (const float*)d_in[5];
    const float* conv_w  = (const float*)d_in[6];
    const float* conv_b  = (const float*)d_in[7];
    const float* ga_W    = (const float*)d_in[8];
    const float* ga_b    = (const float*)d_in[9];
    const float* gx_W    = (const float*)d_in[10];
    const float* gx_b    = (const float*)d_in[11];
    const float* a_param = (const float*)d_in[12];
    const float* out_W   = (const float*)d_in[13];
    const float* out_b   = (const float*)d_in[14];
    const float* norm2_w = (const float*)d_in[15];
    const float* up1_W   = (const float*)d_in[16];
    const float* up1_b   = (const float*)d_in[17];
    const float* up2_W   = (const float*)d_in[18];
    const float* up2_b   = (const float*)d_in[19];
    const float* down_W  = (const float*)d_in[20];
    const float* down_b  = (const float*)d_in[21];
    float* out = (float*)d_out;

    // Opt-in dynamic smem for EXACTLY the instantiations launched below.
    // cudaFuncSetAttribute is not stream-ordered; safe under graph capture,
    // idempotent, no static guards.
    cudaFuncSetAttribute(gemm_kernel<1, 1, false>,
                         cudaFuncAttributeMaxDynamicSharedMemorySize, GEMM_SMEM);
    cudaFuncSetAttribute(gemm_kernel<0, 0, false>,
                         cudaFuncAttributeMaxDynamicSharedMemorySize, GEMM_SMEM);
    cudaFuncSetAttribute(gemm_kernel<2, 2, false>,
                         cudaFuncAttributeMaxDynamicSharedMemorySize, GEMM_SMEM);
    cudaFuncSetAttribute(gemm_kernel<0, 0, true>,
                         cudaFuncAttributeMaxDynamicSharedMemorySize, GEMM_SMEM);

    float* scratch = nullptr;
    cudaGetSymbolAddress((void**)&scratch, g_scratch);
    float* xn   = scratch;          // [TOKENS, D]
    float* left = xn + TD;          // [TOKENS, H]
    float* rp   = left + TD;        // [TOKENS, H]  right pre-conv, later h
    float* cv   = rp + TD;          // [TOKENS, H]  conv out
    float* rg   = cv + TD;          // [TOKENS, H]  r -> a
    float* ig   = rg + TD;          // [TOKENS, H]  i -> b
    float* x1   = ig + TD;          // [TOKENS, D]
    float* x1n  = x1 + TD;          // [TOKENS, D]
    float* f1   = x1n + TD;         // [TOKENS, F]
    float* f2   = f1 + TF;          // [TOKENS, F]

    const int EPI_BLOCKS = 2048;

    // ---- recurrent sub-block ----
    rmsnorm_kernel<<<TOKENS, 256>>>(x, norm1_w, xn, D_DIM);

    launch_gemm<1, 1, false>(xn, left_W, left, H_DIM, left_b,
                             nullptr, 0, nullptr, nullptr,
                             TOKENS, H_DIM, D_DIM, H_DIM);
    launch_gemm<0, 0, false>(xn, right_W, rp, H_DIM, right_b,
                             nullptr, 0, nullptr, nullptr,
                             TOKENS, H_DIM, D_DIM, H_DIM);

    conv_kernel<<<EPI_BLOCKS, 256>>>(rp, conv_w, conv_b, cv);

    launch_gemm<2, 2, false>(cv, ga_W, rg, H_DIM, ga_b,
                             nullptr, 0, nullptr, nullptr,
                             TOKENS, H_DIM, H_DIM, H_DIM);
    launch_gemm<2, 2, false>(cv, gx_W, ig, H_DIM, gx_b,
                             nullptr, 0, nullptr, nullptr,
                             TOKENS, H_DIM, H_DIM, H_DIM);

    ab_kernel<<<EPI_BLOCKS, 256>>>(rg, ig, cv, a_param);

    scan_kernel<<<32, 128>>>(rg, ig, rp);   // h -> rp

    mult_kernel<<<EPI_BLOCKS, 256>>>(left, rp, left, TD);

    launch_gemm<0, 0, true>(left, out_W, x1, D_DIM, out_b,
                            nullptr, 0, nullptr, x,
                            TOKENS, D_DIM, H_DIM, D_DIM);

    // ---- gated MLP sub-block ----
    rmsnorm_kernel<<<TOKENS, 256>>>(x1, norm2_w, x1n, D_DIM);

    launch_gemm<1, 1, false>(x1n, up1_W, f1, F_DIM, up1_b,
                             nullptr, 0, nullptr, nullptr,
                             TOKENS, F_DIM, D_DIM, F_DIM);
    launch_gemm<0, 0, false>(x1n, up2_W, f2, F_DIM, up2_b,
                             nullptr, 0, nullptr, nullptr,
                             TOKENS, F_DIM, D_DIM, F_DIM);

    mult_kernel<<<EPI_BLOCKS, 256>>>(f1, f2, f1, TF);

    launch_gemm<0, 0, true>(f1, down_W, out, D_DIM, down_b,
                            nullptr, 0, nullptr, x1,
                            TOKENS, D_DIM, F_DIM, D_DIM);
}

// round 5
// speedup vs baseline: 5.0171x; 3.8703x over previous
#include <cuda_runtime.h>
#include <cuda_fp16.h>
#include <mma.h>
#include <cstdint>

using namespace nvcuda;

// ============================================================================
// Problem dims (fixed by setup_inputs)
// ============================================================================
#define B_SZ    2
#define S_LEN   2048
#define D_DIM   2048
#define H_DIM   2048
#define F_DIM   6144
#define KCONV   4
#define TOKENS  (B_SZ * S_LEN)   // 4096

#define TD ((size_t)TOKENS * D_DIM)      // 8,388,608
#define TF ((size_t)TOKENS * F_DIM)      // 25,165,824
// fp32 buffers: left, rp, cv, rg, ig, x1 (6*TD) + f1, f2 (2*TF)
// fp16 buffers (counted in floats = half the elem count):
//   xnh, cvh, lhh, x1nh (4 * TD/2 = 2*TD) + f1gh (TF/2)
// fp16 weights: 5*D*H + 3*D*F halves = 58.7M halves = 29.36M floats
#define WH_HALVES ((size_t)5 * D_DIM * H_DIM + 3 * (size_t)D_DIM * F_DIM)
#define SCRATCH_FLOATS (6 * TD + 2 * TF + 2 * TD + TF / 2 + (WH_HALVES + 1) / 2)
__device__ float g_scratch[SCRATCH_FLOATS];

// ============================================================================
// fp16 GEMM: C[M,N] = A[M,K] @ B[K,N], wmma m16n16k16 + cp.async 4-stage.
// Block tile 128x128x32, 256 threads (8 warps), warp tile 32x64.
// Dual-B: CTAs with bn >= Nsplit read B1 / write C1 (concatenated GEMMs).
// Fused epilogue: bias + activation (+ residual), fp32 out.
// ============================================================================
#define BM 128
#define BN 128
#define BK 32
#define STAGES 4
#define LDA_S 40      // halves per A row (32 + 8 pad); 80B, 16B-aligned
#define LDB_S 136     // halves per B row (128 + 8 pad); 272B, 16B-aligned
#define LDC_S 132     // floats per row for epilogue staging
#define A_ST (BM * LDA_S)                     // 5120 halves
#define B_ST (BK * LDB_S)                     // 4352 halves
#define STAGE_HALVES (A_ST + B_ST)            // 9472 halves = 18,944 B
#define PIPE_BYTES (STAGES * STAGE_HALVES * 2)   // 75,776
#define EPI_BYTES (BM * LDC_S * 4)               // 67,584
#define GEMM_SMEM (PIPE_BYTES > EPI_BYTES ? PIPE_BYTES : EPI_BYTES)

__device__ __forceinline__ void cp_async16(uint32_t sdst, const void* gsrc) {
    asm volatile("cp.async.cg.shared.global [%0], [%1], 16;"
                 :: "r"(sdst), "l"(gsrc) : "memory");
}
__device__ __forceinline__ void cp_commit() {
    asm volatile("cp.async.commit_group;" ::: "memory");
}
template <int N>
__device__ __forceinline__ void cp_wait() {
    asm volatile("cp.async.wait_group %0;" :: "n"(N) : "memory");
}

__device__ __forceinline__ float gelu_f(float x) {
    return 0.5f * x * (1.0f + erff(x * 0.70710678118654752440f));
}
__device__ __forceinline__ float sigmoid_f(float x) {
    return 1.0f / (1.0f + expf(-x));
}

// ACT codes: 0 none, 1 gelu, 2 sigmoid
template <int ACT0, int ACT1, bool RES>
__global__ void __launch_bounds__(256, 2)
gemm_h_kernel(const __half* __restrict__ A,
              const __half* __restrict__ B0, const __half* __restrict__ B1,
              float* __restrict__ C0, int ldc0, const float* __restrict__ bias0,
              float* __restrict__ C1, int ldc1, const float* __restrict__ bias1,
              const float* __restrict__ res,
              int M, int K, int Nsplit, int ldb0, int ldb1) {
    extern __shared__ __half smemh[];
    const int tid = threadIdx.x;
    const int warp = tid >> 5;
    const int bm = blockIdx.y * BM;
    const int bn = blockIdx.x * BN;

    // B / output select per CTA
    const bool half1 = (bn >= Nsplit);
    const __half* Bsel = half1 ? B1 : B0;
    const int ldb = half1 ? ldb1 : ldb0;
    const int cb = bn - (half1 ? Nsplit : 0);

    // warp tile 32x64: 4 warp-rows x 2 warp-cols
    const int wm = (warp >> 1) * 32;
    const int wn = (warp & 1) * 64;

    wmma::fragment<wmma::accumulator, 16, 16, 16, float> acc[2][4];
    #pragma unroll
    for (int mi = 0; mi < 2; mi++)
        #pragma unroll
        for (int ni = 0; ni < 4; ni++)
            wmma::fill_fragment(acc[mi][ni], 0.0f);

    const uint32_t smem_u32 = (uint32_t)__cvta_generic_to_shared(smemh);
    const int nk = K / BK;

    const __half* Abase = A + (size_t)bm * K;
    const __half* Bbase = Bsel + cb;

    auto issue_stage = [&](int s, int kc) {
        const uint32_t sA = smem_u32 + (uint32_t)(s * STAGE_HALVES) * 2u;
        const uint32_t sB = sA + (uint32_t)A_ST * 2u;
        const __half* Ab = Abase + (size_t)kc * BK;
        const __half* Bb = Bbase + (size_t)kc * BK * ldb;
        #pragma unroll
        for (int p = 0; p < 2; p++) {       // A: 128 rows x 4 chunks(8h)
            int id = p * 256 + tid;
            int r = id >> 2, c = id & 3;
            cp_async16(sA + (uint32_t)(r * LDA_S + c * 8) * 2u,
                       Ab + (size_t)r * K + c * 8);
        }
        #pragma unroll
        for (int p = 0; p < 2; p++) {       // B: 32 rows x 16 chunks
            int id = p * 256 + tid;
            int r = id >> 4, c = id & 15;
            cp_async16(sB + (uint32_t)(r * LDB_S + c * 8) * 2u,
                       Bb + (size_t)r * ldb + c * 8);
        }
    };

    #pragma unroll
    for (int s = 0; s < STAGES - 1; s++) {
        issue_stage(s, s);
        cp_commit();
    }

    int cur = 0;
    for (int kc = 0; kc < nk; kc++) {
        cp_wait<STAGES - 2>();
        __syncthreads();

        int pf = kc + STAGES - 1;
        if (pf < nk) {
            int s = cur + STAGES - 1;
            if (s >= STAGES) s -= STAGES;
            issue_stage(s, pf);
        }
        cp_commit();

        const __half* sA = smemh + cur * STAGE_HALVES;
        const __half* sB = sA + A_ST;
        #pragma unroll
        for (int kk = 0; kk < BK; kk += 16) {
            wmma::fragment<wmma::matrix_b, 16, 16, 16, __half,
                           wmma::row_major> bf[4];
            #pragma unroll
            for (int ni = 0; ni < 4; ni++)
                wmma::load_matrix_sync(bf[ni],
                                       sB + kk * LDB_S + wn + ni * 16, LDB_S);
            #pragma unroll
            for (int mi = 0; mi < 2; mi++) {
                wmma::fragment<wmma::matrix_a, 16, 16, 16, __half,
                               wmma::row_major> af;
                wmma::load_matrix_sync(af, sA + (wm + mi * 16) * LDA_S + kk,
                                       LDA_S);
                #pragma unroll
                for (int ni = 0; ni < 4; ni++)
                    wmma::mma_sync(acc[mi][ni], af, bf[ni], acc[mi][ni]);
            }
        }
        cur = (cur + 1 == STAGES) ? 0 : cur + 1;
    }

    // ---- fused epilogue via smem ----
    cp_wait<0>();
    __syncthreads();
    float* Cs = reinterpret_cast<float*>(smemh);   // 128 x 132 floats
    #pragma unroll
    for (int mi = 0; mi < 2; mi++)
        #pragma unroll
        for (int ni = 0; ni < 4; ni++)
            wmma::store_matrix_sync(Cs + (wm + mi * 16) * LDC_S + wn + ni * 16,
                                    acc[mi][ni], LDC_S, wmma::mem_row_major);
    __syncthreads();

    float* Cout = half1 ? C1 : C0;
    const int ldc = half1 ? ldc1 : ldc0;
    const float* bias = half1 ? bias1 : bias0;
    const int act = half1 ? ACT1 : ACT0;

    // 256 threads: 2 per row, 64 cols each (16 float4)
    const int r = tid >> 1;
    const int cseg = (tid & 1) * 64;
    const size_t grow = (size_t)(bm + r);
    float* gout = Cout + grow * ldc + cb + cseg;
    const float* biasp = bias + cb + cseg;
    const float* resp = RES ? (res + grow * ldc0 + cb + cseg) : nullptr;
    const float* csrow = Cs + r * LDC_S + cseg;

    #pragma unroll
    for (int j = 0; j < 16; j++) {
        float4 v = *(const float4*)(csrow + j * 4);
        float4 b = *(const float4*)(biasp + j * 4);
        v.x += b.x; v.y += b.y; v.z += b.z; v.w += b.w;
        if (act == 1) {
            v.x = gelu_f(v.x); v.y = gelu_f(v.y);
            v.z = gelu_f(v.z); v.w = gelu_f(v.w);
        } else if (act == 2) {
            v.x = sigmoid_f(v.x); v.y = sigmoid_f(v.y);
            v.z = sigmoid_f(v.z); v.w = sigmoid_f(v.w);
        }
        if (RES) {
            float4 rv = *(const float4*)(resp + j * 4);
            v.x += rv.x; v.y += rv.y; v.z += rv.z; v.w += rv.w;
        }
        *(float4*)(gout + j * 4) = v;
    }
}

// ============================================================================
// Elementwise kernels
// ============================================================================
__global__ void f2h_kernel(const float* __restrict__ in,
                           __half* __restrict__ out, size_t n) {
    for (size_t i = (size_t)blockIdx.x * blockDim.x + threadIdx.x; i < n;
         i += (size_t)gridDim.x * blockDim.x)
        out[i] = __float2half(in[i]);
}

// RMSNorm with fp16 output (GEMM A operand)
__global__ void rmsnorm_h_kernel(const float* __restrict__ x,
                                 const float* __restrict__ w,
                                 __half* __restrict__ out, int D) {
    const float* row = x + (size_t)blockIdx.x * D;
    __half* orow = out + (size_t)blockIdx.x * D;
    float s = 0.0f;
    for (int i = threadIdx.x; i < D; i += blockDim.x) {
        float v = row[i];
        s += v * v;
    }
    #pragma unroll
    for (int off = 16; off > 0; off >>= 1)
        s += __shfl_xor_sync(0xFFFFFFFF, s, off);
    __shared__ float red[32];
    int lane = threadIdx.x & 31, warp = threadIdx.x >> 5;
    if (lane == 0) red[warp] = s;
    __syncthreads();
    int nwarps = blockDim.x >> 5;
    if (warp == 0) {
        float t = (lane < nwarps) ? red[lane] : 0.0f;
        #pragma unroll
        for (int off = 16; off > 0; off >>= 1)
            t += __shfl_xor_sync(0xFFFFFFFF, t, off);
        if (lane == 0) red[0] = t;
    }
    __syncthreads();
    float inv = rsqrtf(red[0] / (float)D + 1e-8f);
    for (int i = threadIdx.x; i < D; i += blockDim.x)
        orow[i] = __float2half(w[i] * row[i] * inv);
}

// conv: fp32 out (for ab) + fp16 out (GEMM A)
__global__ void conv_kernel(const float* __restrict__ x,
                            const float* __restrict__ w,
                            const float* __restrict__ bias,
                            float* __restrict__ y,
                            __half* __restrict__ yh) {
    const size_t total = (size_t)TOKENS * H_DIM;
    for (size_t i = (size_t)blockIdx.x * blockDim.x + threadIdx.x; i < total;
         i += (size_t)gridDim.x * blockDim.x) {
        int h = (int)(i % H_DIM);
        int t = (int)((i / H_DIM) % S_LEN);
        float acc = bias[h];
        #pragma unroll
        for (int k = 0; k < KCONV; k++) {
            int tt = t - (KCONV - 1) + k;
            if (tt >= 0)
                acc += w[k * H_DIM + h] * x[i + (size_t)(tt - t) * H_DIM];
        }
        y[i] = acc;
        yh[i] = __float2half(acc);
    }
}

// r,i already sigmoided (fused in GEMM). Compute a, b in place.
__global__ void ab_kernel(float* __restrict__ rbuf, float* __restrict__ ibuf,
                          const float* __restrict__ xc,
                          const float* __restrict__ ap) {
    const size_t total = (size_t)TOKENS * H_DIM;
    for (size_t i = (size_t)blockIdx.x * blockDim.x + threadIdx.x; i < total;
         i += (size_t)gridDim.x * blockDim.x) {
        int h = (int)(i % H_DIM);
        float sp = log1pf(expf(ap[h]));
        float la = -8.0f * sp * rbuf[i];
        float a = expf(la);
        float mult = sqrtf(-expm1f(2.0f * la));
        rbuf[i] = a;
        ibuf[i] = mult * ibuf[i] * xc[i];
    }
}

__global__ void scan_kernel(const float* __restrict__ a,
                            const float* __restrict__ b,
                            float* __restrict__ hout) {
    int idx = blockIdx.x * blockDim.x + threadIdx.x;
    if (idx >= B_SZ * H_DIM) return;
    int bb = idx / H_DIM;
    int hh = idx % H_DIM;
    size_t base = (size_t)bb * S_LEN * H_DIM + hh;
    float state = 0.0f;
    #pragma unroll 4
    for (int t = 0; t < S_LEN; t++) {
        size_t o = base + (size_t)t * H_DIM;
        state = fmaf(a[o], state, b[o]);
        hout[o] = state;
    }
}

// c_h = half(a * b)
__global__ void mult_h_kernel(const float* __restrict__ a,
                              const float* __restrict__ b,
                              __half* __restrict__ c, size_t total) {
    for (size_t i = (size_t)blockIdx.x * blockDim.x + threadIdx.x; i < total;
         i += (size_t)gridDim.x * blockDim.x)
        c[i] = __float2half(a[i] * b[i]);
}

// ============================================================================
// Host launch
// ============================================================================
template <int ACT0, int ACT1, bool RES>
static inline void launch_gemm(const __half* A,
                               const __half* B0, const __half* B1,
                               float* C0, int ldc0, const float* bias0,
                               float* C1, int ldc1, const float* bias1,
                               const float* res,
                               int M, int Ntot, int K, int Nsplit,
                               int ldb0, int ldb1) {
    dim3 grid(Ntot / BN, M / BM);
    gemm_h_kernel<ACT0, ACT1, RES><<<grid, 256, GEMM_SMEM>>>(
        A, B0, B1, C0, ldc0, bias0, C1, ldc1, bias1, res,
        M, K, Nsplit, ldb0, ldb1);
}

extern "C" void kernel_launch(void* const* d_in, const int* in_sizes, int n_in,
                              void* d_out, int out_size) {
    (void)in_sizes; (void)n_in; (void)out_size;
    const float* x       = (const float*)d_in[0];
    const float* norm1_w = (const float*)d_in[1];
    const float* left_W  = (const float*)d_in[2];
    const float* left_b  = (const float*)d_in[3];
    const float* right_W = (const float*)d_in[4];
    const float* right_b = (const float*)d_in[5];
    const float* conv_w  = (const float*)d_in[6];
    const float* conv_b  = (const float*)d_in[7];
    const float* ga_W    = (const float*)d_in[8];
    const float* ga_b    = (const float*)d_in[9];
    const float* gx_W    = (const float*)d_in[10];
    const float* gx_b    = (const float*)d_in[11];
    const float* a_param = (const float*)d_in[12];
    const float* out_W   = (const float*)d_in[13];
    const float* out_b   = (const float*)d_in[14];
    const float* norm2_w = (const float*)d_in[15];
    const float* up1_W   = (const float*)d_in[16];
    const float* up1_b   = (const float*)d_in[17];
    const float* up2_W   = (const float*)d_in[18];
    const float* up2_b   = (const float*)d_in[19];
    const float* down_W  = (const float*)d_in[20];
    const float* down_b  = (const float*)d_in[21];
    float* out = (float*)d_out;

    // dynamic smem opt-in for exactly the instantiations launched below
    cudaFuncSetAttribute(gemm_h_kernel<1, 0, false>,
                         cudaFuncAttributeMaxDynamicSharedMemorySize, GEMM_SMEM);
    cudaFuncSetAttribute(gemm_h_kernel<2, 2, false>,
                         cudaFuncAttributeMaxDynamicSharedMemorySize, GEMM_SMEM);
    cudaFuncSetAttribute(gemm_h_kernel<0, 0, true>,
                         cudaFuncAttributeMaxDynamicSharedMemorySize, GEMM_SMEM);

    float* scratch = nullptr;
    cudaGetSymbolAddress((void**)&scratch, g_scratch);
    // fp32 buffers
    float* left = scratch;          // [TOKENS, H]
    float* rp   = left + TD;        // [TOKENS, H]  right pre-conv, later h
    float* cv   = rp + TD;          // [TOKENS, H]
    float* rg   = cv + TD;          // [TOKENS, H]  r -> a
    float* ig   = rg + TD;          // [TOKENS, H]  i -> b
    float* x1   = ig + TD;          // [TOKENS, D]
    float* f1   = x1 + TD;          // [TOKENS, F]
    float* f2   = f1 + TF;          // [TOKENS, F]
    // fp16 buffers
    __half* xnh  = (__half*)(f2 + TF);          // [TOKENS, D]
    __half* cvh  = xnh + TD;                    // [TOKENS, H]
    __half* lhh  = cvh + TD;                    // [TOKENS, H]
    __half* x1nh = lhh + TD;                    // [TOKENS, D]
    __half* f1gh = x1nh + TD;                   // [TOKENS, F]
    __half* wh   = f1gh + TF;
    __half* leftWh  = wh;                                    // [D,H]
    __half* rightWh = leftWh  + (size_t)D_DIM * H_DIM;       // [D,H]
    __half* gaWh    = rightWh + (size_t)D_DIM * H_DIM;       // [H,H]
    __half* gxWh    = gaWh    + (size_t)H_DIM * H_DIM;       // [H,H]
    __half* outWh   = gxWh    + (size_t)H_DIM * H_DIM;       // [H,D]
    __half* up1Wh   = outWh   + (size_t)H_DIM * D_DIM;       // [D,F]
    __half* up2Wh   = up1Wh   + (size_t)D_DIM * F_DIM;       // [D,F]
    __half* downWh  = up2Wh   + (size_t)D_DIM * F_DIM;       // [F,D]

    const int EPI_BLOCKS = 2048;
    const int CVT_BLOCKS = 1024;

    // ---- weight conversion (fp32 -> fp16) ----
    f2h_kernel<<<CVT_BLOCKS, 256>>>(left_W,  leftWh,  (size_t)D_DIM * H_DIM);
    f2h_kernel<<<CVT_BLOCKS, 256>>>(right_W, rightWh, (size_t)D_DIM * H_DIM);
    f2h_kernel<<<CVT_BLOCKS, 256>>>(ga_W,    gaWh,    (size_t)H_DIM * H_DIM);
    f2h_kernel<<<CVT_BLOCKS, 256>>>(gx_W,    gxWh,    (size_t)H_DIM * H_DIM);
    f2h_kernel<<<CVT_BLOCKS, 256>>>(out_W,   outWh,   (size_t)H_DIM * D_DIM);
    f2h_kernel<<<CVT_BLOCKS, 256>>>(up1_W,   up1Wh,   (size_t)D_DIM * F_DIM);
    f2h_kernel<<<CVT_BLOCKS, 256>>>(up2_W,   up2Wh,   (size_t)D_DIM * F_DIM);
    f2h_kernel<<<CVT_BLOCKS, 256>>>(down_W,  downWh,  (size_t)F_DIM * D_DIM);

    // ---- recurrent sub-block ----
    rmsnorm_h_kernel<<<TOKENS, 256>>>(x, norm1_w, xnh, D_DIM);

    // left|right fused: N = 2048+2048
    launch_gemm<1, 0, false>(xnh, leftWh, rightWh,
                             left, H_DIM, left_b, rp, H_DIM, right_b, nullptr,
                             TOKENS, 2 * H_DIM, D_DIM, H_DIM, H_DIM, H_DIM);

    conv_kernel<<<EPI_BLOCKS, 256>>>(rp, conv_w, conv_b, cv, cvh);

    // ga|gx fused, both sigmoid
    launch_gemm<2, 2, false>(cvh, gaWh, gxWh,
                             rg, H_DIM, ga_b, ig, H_DIM, gx_b, nullptr,
                             TOKENS, 2 * H_DIM, H_DIM, H_DIM, H_DIM, H_DIM);

    ab_kernel<<<EPI_BLOCKS, 256>>>(rg, ig, cv, a_param);

    scan_kernel<<<32, 128>>>(rg, ig, rp);   // h -> rp

    mult_h_kernel<<<EPI_BLOCKS, 256>>>(left, rp, lhh, TD);

    launch_gemm<0, 0, true>(lhh, outWh, outWh,
                            x1, D_DIM, out_b, nullptr, 0, nullptr, x,
                            TOKENS, D_DIM, H_DIM, D_DIM, D_DIM, D_DIM);

    // ---- gated MLP sub-block ----
    rmsnorm_h_kernel<<<TOKENS, 256>>>(x1, norm2_w, x1nh, D_DIM);

    // up1|up2 fused: N = 6144+6144, up1 gelu
    launch_gemm<1, 0, false>(x1nh, up1Wh, up2Wh,
                             f1, F_DIM, up1_b, f2, F_DIM, up2_b, nullptr,
                             TOKENS, 2 * F_DIM, D_DIM, F_DIM, F_DIM, F_DIM);

    mult_h_kernel<<<EPI_BLOCKS, 256>>>(f1, f2, f1gh, TF);

    launch_gemm<0, 0, true>(f1gh, downWh, downWh,
                            out, D_DIM, down_b, nullptr, 0, nullptr, x1,
                            TOKENS, D_DIM, F_DIM, D_DIM, D_DIM, D_DIM);
}

// round 6
// speedup vs baseline: 5.2328x; 1.0430x over previous
#include <cuda_runtime.h>
#include <cuda_fp16.h>
#include <mma.h>
#include <cstdint>

using namespace nvcuda;

// ============================================================================
// Problem dims (fixed by setup_inputs)
// ============================================================================
#define B_SZ    2
#define S_LEN   2048
#define D_DIM   2048
#define H_DIM   2048
#define F_DIM   6144
#define KCONV   4
#define TOKENS  (B_SZ * S_LEN)   // 4096

#define TD ((size_t)TOKENS * D_DIM)      // 8,388,608
#define TF ((size_t)TOKENS * F_DIM)      // 25,165,824
// fp32: left, rp, cv, a, b, x1 (6*TD)
// fp16 (in float units): xnh, cvh, lhh, x1nh (4*TD/2=2*TD) + f1gh (TF/2)
// fp16 weights: (5*D*H + 3*D*F)/2 floats
#define WH_HALVES ((size_t)5 * D_DIM * H_DIM + 3 * (size_t)D_DIM * F_DIM)
#define SCRATCH_FLOATS (6 * TD + 2 * TD + TF / 2 + (WH_HALVES + 1) / 2)
__device__ float g_scratch[SCRATCH_FLOATS];

// ============================================================================
// common helpers
// ============================================================================
__device__ __forceinline__ void cp_async16(uint32_t sdst, const void* gsrc) {
    asm volatile("cp.async.cg.shared.global [%0], [%1], 16;"
                 :: "r"(sdst), "l"(gsrc) : "memory");
}
__device__ __forceinline__ void cp_commit() {
    asm volatile("cp.async.commit_group;" ::: "memory");
}
template <int N>
__device__ __forceinline__ void cp_wait() {
    asm volatile("cp.async.wait_group %0;" :: "n"(N) : "memory");
}
__device__ __forceinline__ float gelu_f(float x) {
    return 0.5f * x * (1.0f + erff(x * 0.70710678118654752440f));
}
__device__ __forceinline__ float sigmoid_f(float x) {
    return 1.0f / (1.0f + expf(-x));
}

// ============================================================================
// Single-output fp16 GEMM (dual-B scatter by Nsplit), fused epilogue.
// Tile 128x128x32, 256 threads, 4-stage cp.async. (Round-5 kernel.)
// ============================================================================
#define BM 128
#define BN 128
#define BK 32
#define STAGES 4
#define LDA_S 40
#define LDB_S 136
#define LDC_S 132
#define A_ST (BM * LDA_S)                     // 5120 halves
#define B_ST (BK * LDB_S)                     // 4352 halves
#define STAGE_HALVES (A_ST + B_ST)            // 9472
#define PIPE_BYTES (STAGES * STAGE_HALVES * 2)   // 75,776
#define EPI_BYTES (BM * LDC_S * 4)               // 67,584
#define GEMM_SMEM (PIPE_BYTES > EPI_BYTES ? PIPE_BYTES : EPI_BYTES)

// ACT: 0 none, 1 gelu
template <int ACT0, int ACT1, bool RES>
__global__ void __launch_bounds__(256, 2)
gemm_h_kernel(const __half* __restrict__ A,
              const __half* __restrict__ B0, const __half* __restrict__ B1,
              float* __restrict__ C0, int ldc0, const float* __restrict__ bias0,
              float* __restrict__ C1, int ldc1, const float* __restrict__ bias1,
              const float* __restrict__ res,
              int M, int K, int Nsplit, int ldb0, int ldb1) {
    extern __shared__ __half smemh[];
    const int tid = threadIdx.x;
    const int warp = tid >> 5;
    const int bm = blockIdx.y * BM;
    const int bn = blockIdx.x * BN;

    const bool half1 = (bn >= Nsplit);
    const __half* Bsel = half1 ? B1 : B0;
    const int ldb = half1 ? ldb1 : ldb0;
    const int cb = bn - (half1 ? Nsplit : 0);

    const int wm = (warp >> 1) * 32;
    const int wn = (warp & 1) * 64;

    wmma::fragment<wmma::accumulator, 16, 16, 16, float> acc[2][4];
    #pragma unroll
    for (int mi = 0; mi < 2; mi++)
        #pragma unroll
        for (int ni = 0; ni < 4; ni++)
            wmma::fill_fragment(acc[mi][ni], 0.0f);

    const uint32_t smem_u32 = (uint32_t)__cvta_generic_to_shared(smemh);
    const int nk = K / BK;
    const __half* Abase = A + (size_t)bm * K;
    const __half* Bbase = Bsel + cb;

    auto issue_stage = [&](int s, int kc) {
        const uint32_t sA = smem_u32 + (uint32_t)(s * STAGE_HALVES) * 2u;
        const uint32_t sB = sA + (uint32_t)A_ST * 2u;
        const __half* Ab = Abase + (size_t)kc * BK;
        const __half* Bb = Bbase + (size_t)kc * BK * ldb;
        #pragma unroll
        for (int p = 0; p < 2; p++) {
            int id = p * 256 + tid;
            int r = id >> 2, c = id & 3;
            cp_async16(sA + (uint32_t)(r * LDA_S + c * 8) * 2u,
                       Ab + (size_t)r * K + c * 8);
        }
        #pragma unroll
        for (int p = 0; p < 2; p++) {
            int id = p * 256 + tid;
            int r = id >> 4, c = id & 15;
            cp_async16(sB + (uint32_t)(r * LDB_S + c * 8) * 2u,
                       Bb + (size_t)r * ldb + c * 8);
        }
    };

    #pragma unroll
    for (int s = 0; s < STAGES - 1; s++) { issue_stage(s, s); cp_commit(); }

    int cur = 0;
    for (int kc = 0; kc < nk; kc++) {
        cp_wait<STAGES - 2>();
        __syncthreads();
        int pf = kc + STAGES - 1;
        if (pf < nk) {
            int s = cur + STAGES - 1;
            if (s >= STAGES) s -= STAGES;
            issue_stage(s, pf);
        }
        cp_commit();

        const __half* sA = smemh + cur * STAGE_HALVES;
        const __half* sB = sA + A_ST;
        #pragma unroll
        for (int kk = 0; kk < BK; kk += 16) {
            wmma::fragment<wmma::matrix_b, 16, 16, 16, __half,
                           wmma::row_major> bf[4];
            #pragma unroll
            for (int ni = 0; ni < 4; ni++)
                wmma::load_matrix_sync(bf[ni], sB + kk * LDB_S + wn + ni * 16,
                                       LDB_S);
            #pragma unroll
            for (int mi = 0; mi < 2; mi++) {
                wmma::fragment<wmma::matrix_a, 16, 16, 16, __half,
                               wmma::row_major> af;
                wmma::load_matrix_sync(af, sA + (wm + mi * 16) * LDA_S + kk,
                                       LDA_S);
                #pragma unroll
                for (int ni = 0; ni < 4; ni++)
                    wmma::mma_sync(acc[mi][ni], af, bf[ni], acc[mi][ni]);
            }
        }
        cur = (cur + 1 == STAGES) ? 0 : cur + 1;
    }

    cp_wait<0>();
    __syncthreads();
    float* Cs = reinterpret_cast<float*>(smemh);
    #pragma unroll
    for (int mi = 0; mi < 2; mi++)
        #pragma unroll
        for (int ni = 0; ni < 4; ni++)
            wmma::store_matrix_sync(Cs + (wm + mi * 16) * LDC_S + wn + ni * 16,
                                    acc[mi][ni], LDC_S, wmma::mem_row_major);
    __syncthreads();

    float* Cout = half1 ? C1 : C0;
    const int ldc = half1 ? ldc1 : ldc0;
    const float* bias = half1 ? bias1 : bias0;
    const int act = half1 ? ACT1 : ACT0;

    const int r = tid >> 1;
    const int cseg = (tid & 1) * 64;
    const size_t grow = (size_t)(bm + r);
    float* gout = Cout + grow * ldc + cb + cseg;
    const float* biasp = bias + cb + cseg;
    const float* resp = RES ? (res + grow * ldc0 + cb + cseg) : nullptr;
    const float* csrow = Cs + r * LDC_S + cseg;

    #pragma unroll
    for (int j = 0; j < 16; j++) {
        float4 v = *(const float4*)(csrow + j * 4);
        float4 b = *(const float4*)(biasp + j * 4);
        v.x += b.x; v.y += b.y; v.z += b.z; v.w += b.w;
        if (act == 1) {
            v.x = gelu_f(v.x); v.y = gelu_f(v.y);
            v.z = gelu_f(v.z); v.w = gelu_f(v.w);
        }
        if (RES) {
            float4 rv = *(const float4*)(resp + j * 4);
            v.x += rv.x; v.y += rv.y; v.z += rv.z; v.w += rv.w;
        }
        *(float4*)(gout + j * 4) = v;
    }
}

// ============================================================================
// Dual-accumulator GEMM: one CTA computes the SAME N columns of A@B0 and
// A@B1, combining both in the epilogue (no fp32 round-trip to GMEM).
// Tile 128 x 64(x2) x 32, 256 threads, 4-stage cp.async.
// COMBINE 0 (GLU): out0h[m,n] = half( gelu(v0+bias0) * (v1+bias1) )
// COMBINE 1 (AB):  r=sig(v0+bias0), i=sig(v1+bias1),
//                  la=-8*softplus(ap[n])*r, a=exp(la),
//                  b=sqrt(-expm1(2la))*i*xc[m,n]; out0f=a, out1f=b
// ============================================================================
#define BND 64
#define LDBD 72
#define B_STD (BK * LDBD)                       // 2304 halves
#define STAGE_D (A_ST + 2 * B_STD)              // 9728 halves
#define PIPE_D_BYTES (STAGES * STAGE_D * 2)     // 77,824
#define LDC_D 68
#define EPI_D_BYTES (2 * BM * LDC_D * 4)        // 69,632
#define GEMM_D_SMEM (PIPE_D_BYTES > EPI_D_BYTES ? PIPE_D_BYTES : EPI_D_BYTES)

template <int COMBINE>
__global__ void __launch_bounds__(256, 2)
gemm_dual_kernel(const __half* __restrict__ A,
                 const __half* __restrict__ B0, const __half* __restrict__ B1,
                 __half* __restrict__ out0h,
                 float* __restrict__ out0f, float* __restrict__ out1f,
                 const float* __restrict__ bias0,
                 const float* __restrict__ bias1,
                 const float* __restrict__ xc, const float* __restrict__ ap,
                 int M, int N, int K, int ldb) {
    extern __shared__ __half smemh[];
    const int tid = threadIdx.x;
    const int warp = tid >> 5;
    const int bm = blockIdx.y * BM;
    const int bn = blockIdx.x * BND;

    const int wm = (warp >> 1) * 32;
    const int wn = (warp & 1) * 32;

    wmma::fragment<wmma::accumulator, 16, 16, 16, float> acc0[2][2], acc1[2][2];
    #pragma unroll
    for (int mi = 0; mi < 2; mi++)
        #pragma unroll
        for (int ni = 0; ni < 2; ni++) {
            wmma::fill_fragment(acc0[mi][ni], 0.0f);
            wmma::fill_fragment(acc1[mi][ni], 0.0f);
        }

    const uint32_t smem_u32 = (uint32_t)__cvta_generic_to_shared(smemh);
    const int nk = K / BK;
    const __half* Abase = A + (size_t)bm * K;
    const __half* B0base = B0 + bn;
    const __half* B1base = B1 + bn;

    auto issue_stage = [&](int s, int kc) {
        const uint32_t sA = smem_u32 + (uint32_t)(s * STAGE_D) * 2u;
        const uint32_t sB0 = sA + (uint32_t)A_ST * 2u;
        const uint32_t sB1 = sB0 + (uint32_t)B_STD * 2u;
        const __half* Ab = Abase + (size_t)kc * BK;
        const size_t brow = (size_t)kc * BK * ldb;
        #pragma unroll
        for (int p = 0; p < 2; p++) {       // A: 128 rows x 4 chunks
            int id = p * 256 + tid;
            int r = id >> 2, c = id & 3;
            cp_async16(sA + (uint32_t)(r * LDA_S + c * 8) * 2u,
                       Ab + (size_t)r * K + c * 8);
        }
        {                                   // B0: 32 rows x 8 chunks
            int r = tid >> 3, c = tid & 7;
            cp_async16(sB0 + (uint32_t)(r * LDBD + c * 8) * 2u,
                       B0base + brow + (size_t)r * ldb + c * 8);
            cp_async16(sB1 + (uint32_t)(r * LDBD + c * 8) * 2u,
                       B1base + brow + (size_t)r * ldb + c * 8);
        }
    };

    #pragma unroll
    for (int s = 0; s < STAGES - 1; s++) { issue_stage(s, s); cp_commit(); }

    int cur = 0;
    for (int kc = 0; kc < nk; kc++) {
        cp_wait<STAGES - 2>();
        __syncthreads();
        int pf = kc + STAGES - 1;
        if (pf < nk) {
            int s = cur + STAGES - 1;
            if (s >= STAGES) s -= STAGES;
            issue_stage(s, pf);
        }
        cp_commit();

        const __half* sA = smemh + cur * STAGE_D;
        const __half* sB0 = sA + A_ST;
        const __half* sB1 = sB0 + B_STD;
        #pragma unroll
        for (int kk = 0; kk < BK; kk += 16) {
            wmma::fragment<wmma::matrix_b, 16, 16, 16, __half,
                           wmma::row_major> b0f[2], b1f[2];
            #pragma unroll
            for (int ni = 0; ni < 2; ni++) {
                wmma::load_matrix_sync(b0f[ni], sB0 + kk * LDBD + wn + ni * 16,
                                       LDBD);
                wmma::load_matrix_sync(b1f[ni], sB1 + kk * LDBD + wn + ni * 16,
                                       LDBD);
            }
            #pragma unroll
            for (int mi = 0; mi < 2; mi++) {
                wmma::fragment<wmma::matrix_a, 16, 16, 16, __half,
                               wmma::row_major> af;
                wmma::load_matrix_sync(af, sA + (wm + mi * 16) * LDA_S + kk,
                                       LDA_S);
                #pragma unroll
                for (int ni = 0; ni < 2; ni++) {
                    wmma::mma_sync(acc0[mi][ni], af, b0f[ni], acc0[mi][ni]);
                    wmma::mma_sync(acc1[mi][ni], af, b1f[ni], acc1[mi][ni]);
                }
            }
        }
        cur = (cur + 1 == STAGES) ? 0 : cur + 1;
    }

    cp_wait<0>();
    __syncthreads();
    float* Cs0 = reinterpret_cast<float*>(smemh);
    float* Cs1 = Cs0 + BM * LDC_D;
    #pragma unroll
    for (int mi = 0; mi < 2; mi++)
        #pragma unroll
        for (int ni = 0; ni < 2; ni++) {
            wmma::store_matrix_sync(Cs0 + (wm + mi * 16) * LDC_D + wn + ni * 16,
                                    acc0[mi][ni], LDC_D, wmma::mem_row_major);
            wmma::store_matrix_sync(Cs1 + (wm + mi * 16) * LDC_D + wn + ni * 16,
                                    acc1[mi][ni], LDC_D, wmma::mem_row_major);
        }
    __syncthreads();

    // 256 threads: 2 per row, 32 cols each (8 float4 groups)
    const int r = tid >> 1;
    const int c0 = (tid & 1) * 32;
    const size_t row = (size_t)(bm + r);
    const int gcol = bn + c0;

    #pragma unroll
    for (int j = 0; j < 8; j++) {
        const int cc = c0 + j * 4;
        float4 v0 = *(const float4*)(Cs0 + r * LDC_D + cc);
        float4 v1 = *(const float4*)(Cs1 + r * LDC_D + cc);
        float4 b0 = *(const float4*)(bias0 + gcol + j * 4);
        float4 b1 = *(const float4*)(bias1 + gcol + j * 4);
        v0.x += b0.x; v0.y += b0.y; v0.z += b0.z; v0.w += b0.w;
        v1.x += b1.x; v1.y += b1.y; v1.z += b1.z; v1.w += b1.w;
        if (COMBINE == 0) {
            // GLU: half( gelu(v0) * v1 )
            float4 p;
            p.x = gelu_f(v0.x) * v1.x;
            p.y = gelu_f(v0.y) * v1.y;
            p.z = gelu_f(v0.z) * v1.z;
            p.w = gelu_f(v0.w) * v1.w;
            __half2 h01 = __floats2half2_rn(p.x, p.y);
            __half2 h23 = __floats2half2_rn(p.z, p.w);
            __half2* dst = (__half2*)(out0h + row * N + gcol + j * 4);
            dst[0] = h01;
            dst[1] = h23;
        } else {
            // AB: a = exp(-8*softplus(ap)*sig(v0)); b = sqrt(-expm1(2la))*sig(v1)*xc
            float4 apv = *(const float4*)(ap + gcol + j * 4);
            float4 xcv = *(const float4*)(xc + row * N + gcol + j * 4);
            float4 av, bv;
            {
                float rr = sigmoid_f(v0.x), ii = sigmoid_f(v1.x);
                float la = -8.0f * log1pf(expf(apv.x)) * rr;
                av.x = expf(la);
                bv.x = sqrtf(-expm1f(2.0f * la)) * ii * xcv.x;
            }
            {
                float rr = sigmoid_f(v0.y), ii = sigmoid_f(v1.y);
                float la = -8.0f * log1pf(expf(apv.y)) * rr;
                av.y = expf(la);
                bv.y = sqrtf(-expm1f(2.0f * la)) * ii * xcv.y;
            }
            {
                float rr = sigmoid_f(v0.z), ii = sigmoid_f(v1.z);
                float la = -8.0f * log1pf(expf(apv.z)) * rr;
                av.z = expf(la);
                bv.z = sqrtf(-expm1f(2.0f * la)) * ii * xcv.z;
            }
            {
                float rr = sigmoid_f(v0.w), ii = sigmoid_f(v1.w);
                float la = -8.0f * log1pf(expf(apv.w)) * rr;
                av.w = expf(la);
                bv.w = sqrtf(-expm1f(2.0f * la)) * ii * xcv.w;
            }
            *(float4*)(out0f + row * N + gcol + j * 4) = av;
            *(float4*)(out1f + row * N + gcol + j * 4) = bv;
        }
    }
}

// ============================================================================
// Elementwise kernels
// ============================================================================
__global__ void f2h_kernel(const float* __restrict__ in,
                           __half* __restrict__ out, size_t n) {
    for (size_t i = (size_t)blockIdx.x * blockDim.x + threadIdx.x; i < n;
         i += (size_t)gridDim.x * blockDim.x)
        out[i] = __float2half(in[i]);
}

__global__ void rmsnorm_h_kernel(const float* __restrict__ x,
                                 const float* __restrict__ w,
                                 __half* __restrict__ out, int D) {
    const float* row = x + (size_t)blockIdx.x * D;
    __half* orow = out + (size_t)blockIdx.x * D;
    float s = 0.0f;
    for (int i = threadIdx.x; i < D; i += blockDim.x) {
        float v = row[i];
        s += v * v;
    }
    #pragma unroll
    for (int off = 16; off > 0; off >>= 1)
        s += __shfl_xor_sync(0xFFFFFFFF, s, off);
    __shared__ float red[32];
    int lane = threadIdx.x & 31, warp = threadIdx.x >> 5;
    if (lane == 0) red[warp] = s;
    __syncthreads();
    int nwarps = blockDim.x >> 5;
    if (warp == 0) {
        float t = (lane < nwarps) ? red[lane] : 0.0f;
        #pragma unroll
        for (int off = 16; off > 0; off >>= 1)
            t += __shfl_xor_sync(0xFFFFFFFF, t, off);
        if (lane == 0) red[0] = t;
    }
    __syncthreads();
    float inv = rsqrtf(red[0] / (float)D + 1e-8f);
    for (int i = threadIdx.x; i < D; i += blockDim.x)
        orow[i] = __float2half(w[i] * row[i] * inv);
}

__global__ void conv_kernel(const float* __restrict__ x,
                            const float* __restrict__ w,
                            const float* __restrict__ bias,
                            float* __restrict__ y,
                            __half* __restrict__ yh) {
    const size_t total = (size_t)TOKENS * H_DIM;
    for (size_t i = (size_t)blockIdx.x * blockDim.x + threadIdx.x; i < total;
         i += (size_t)gridDim.x * blockDim.x) {
        int h = (int)(i % H_DIM);
        int t = (int)((i / H_DIM) % S_LEN);
        float acc = bias[h];
        #pragma unroll
        for (int k = 0; k < KCONV; k++) {
            int tt = t - (KCONV - 1) + k;
            if (tt >= 0)
                acc += w[k * H_DIM + h] * x[i + (size_t)(tt - t) * H_DIM];
        }
        y[i] = acc;
        yh[i] = __float2half(acc);
    }
}

// fused scan + gate-multiply: h_t = a_t h_{t-1} + b_t;  lh = half(left * h)
__global__ void scan_mult_kernel(const float* __restrict__ a,
                                 const float* __restrict__ b,
                                 const float* __restrict__ left,
                                 __half* __restrict__ lh) {
    int idx = blockIdx.x * blockDim.x + threadIdx.x;
    if (idx >= B_SZ * H_DIM) return;
    int bb = idx / H_DIM;
    int hh = idx % H_DIM;
    size_t base = (size_t)bb * S_LEN * H_DIM + hh;
    float state = 0.0f;
    #pragma unroll 4
    for (int t = 0; t < S_LEN; t++) {
        size_t o = base + (size_t)t * H_DIM;
        state = fmaf(a[o], state, b[o]);
        lh[o] = __float2half(left[o] * state);
    }
}

// ============================================================================
// Host launch
// ============================================================================
template <int ACT0, int ACT1, bool RES>
static inline void launch_gemm(const __half* A,
                               const __half* B0, const __half* B1,
                               float* C0, int ldc0, const float* bias0,
                               float* C1, int ldc1, const float* bias1,
                               const float* res,
                               int M, int Ntot, int K, int Nsplit,
                               int ldb0, int ldb1) {
    dim3 grid(Ntot / BN, M / BM);
    gemm_h_kernel<ACT0, ACT1, RES><<<grid, 256, GEMM_SMEM>>>(
        A, B0, B1, C0, ldc0, bias0, C1, ldc1, bias1, res,
        M, K, Nsplit, ldb0, ldb1);
}

extern "C" void kernel_launch(void* const* d_in, const int* in_sizes, int n_in,
                              void* d_out, int out_size) {
    (void)in_sizes; (void)n_in; (void)out_size;
    const float* x       = (const float*)d_in[0];
    const float* norm1_w = (const float*)d_in[1];
    const float* left_W  = (const float*)d_in[2];
    const float* left_b  = (const float*)d_in[3];
    const float* right_W = (const float*)d_in[4];
    const float* right_b = (const float*)d_in[5];
    const float* conv_w  = (const float*)d_in[6];
    const float* conv_b  = (const float*)d_in[7];
    const float* ga_W    = (const float*)d_in[8];
    const float* ga_b    = (const float*)d_in[9];
    const float* gx_W    = (const float*)d_in[10];
    const float* gx_b    = (const float*)d_in[11];
    const float* a_param = (const float*)d_in[12];
    const float* out_W   = (const float*)d_in[13];
    const float* out_b   = (const float*)d_in[14];
    const float* norm2_w = (const float*)d_in[15];
    const float* up1_W   = (const float*)d_in[16];
    const float* up1_b   = (const float*)d_in[17];
    const float* up2_W   = (const float*)d_in[18];
    const float* up2_b   = (const float*)d_in[19];
    const float* down_W  = (const float*)d_in[20];
    const float* down_b  = (const float*)d_in[21];
    float* out = (float*)d_out;

    // dynamic smem opt-in for exactly the instantiations launched below
    cudaFuncSetAttribute(gemm_h_kernel<1, 0, false>,
                         cudaFuncAttributeMaxDynamicSharedMemorySize, GEMM_SMEM);
    cudaFuncSetAttribute(gemm_h_kernel<0, 0, true>,
                         cudaFuncAttributeMaxDynamicSharedMemorySize, GEMM_SMEM);
    cudaFuncSetAttribute(gemm_dual_kernel<0>,
                         cudaFuncAttributeMaxDynamicSharedMemorySize, GEMM_D_SMEM);
    cudaFuncSetAttribute(gemm_dual_kernel<1>,
                         cudaFuncAttributeMaxDynamicSharedMemorySize, GEMM_D_SMEM);

    float* scratch = nullptr;
    cudaGetSymbolAddress((void**)&scratch, g_scratch);
    // fp32 buffers
    float* left = scratch;          // [TOKENS, H]
    float* rp   = left + TD;        // [TOKENS, H]  right pre-conv
    float* cv   = rp + TD;          // [TOKENS, H]  conv out (xc)
    float* abuf = cv + TD;          // [TOKENS, H]  a
    float* bbuf = abuf + TD;        // [TOKENS, H]  b
    float* x1   = bbuf + TD;        // [TOKENS, D]
    // fp16 buffers
    __half* xnh  = (__half*)(x1 + TD);          // [TOKENS, D]
    __half* cvh  = xnh + TD;                    // [TOKENS, H]
    __half* lhh  = cvh + TD;                    // [TOKENS, H]
    __half* x1nh = lhh + TD;                    // [TOKENS, D]
    __half* f1gh = x1nh + TD;                   // [TOKENS, F]
    __half* wh   = f1gh + TF;
    __half* leftWh  = wh;                                    // [D,H]
    __half* rightWh = leftWh  + (size_t)D_DIM * H_DIM;       // [D,H]
    __half* gaWh    = rightWh + (size_t)D_DIM * H_DIM;       // [H,H]
    __half* gxWh    = gaWh    + (size_t)H_DIM * H_DIM;       // [H,H]
    __half* outWh   = gxWh    + (size_t)H_DIM * H_DIM;       // [H,D]
    __half* up1Wh   = outWh   + (size_t)H_DIM * D_DIM;       // [D,F]
    __half* up2Wh   = up1Wh   + (size_t)D_DIM * F_DIM;       // [D,F]
    __half* downWh  = up2Wh   + (size_t)D_DIM * F_DIM;       // [F,D]

    const int EPI_BLOCKS = 2048;
    const int CVT_BLOCKS = 1024;

    // ---- weight conversion (fp32 -> fp16) ----
    f2h_kernel<<<CVT_BLOCKS, 256>>>(left_W,  leftWh,  (size_t)D_DIM * H_DIM);
    f2h_kernel<<<CVT_BLOCKS, 256>>>(right_W, rightWh, (size_t)D_DIM * H_DIM);
    f2h_kernel<<<CVT_BLOCKS, 256>>>(ga_W,    gaWh,    (size_t)H_DIM * H_DIM);
    f2h_kernel<<<CVT_BLOCKS, 256>>>(gx_W,    gxWh,    (size_t)H_DIM * H_DIM);
    f2h_kernel<<<CVT_BLOCKS, 256>>>(out_W,   outWh,   (size_t)H_DIM * D_DIM);
    f2h_kernel<<<CVT_BLOCKS, 256>>>(up1_W,   up1Wh,   (size_t)D_DIM * F_DIM);
    f2h_kernel<<<CVT_BLOCKS, 256>>>(up2_W,   up2Wh,   (size_t)D_DIM * F_DIM);
    f2h_kernel<<<CVT_BLOCKS, 256>>>(down_W,  downWh,  (size_t)F_DIM * D_DIM);

    // ---- recurrent sub-block ----
    rmsnorm_h_kernel<<<TOKENS, 256>>>(x, norm1_w, xnh, D_DIM);

    // left|right (scatter): left = gelu(xn@left_W + b), rp = xn@right_W + b
    launch_gemm<1, 0, false>(xnh, leftWh, rightWh,
                             left, H_DIM, left_b, rp, H_DIM, right_b, nullptr,
                             TOKENS, 2 * H_DIM, D_DIM, H_DIM, H_DIM, H_DIM);

    conv_kernel<<<EPI_BLOCKS, 256>>>(rp, conv_w, conv_b, cv, cvh);

    // ga|gx dual with fused RG-LRU gate math -> a, b
    {
        dim3 grid(H_DIM / BND, TOKENS / BM);
        gemm_dual_kernel<1><<<grid, 256, GEMM_D_SMEM>>>(
            cvh, gaWh, gxWh, nullptr, abuf, bbuf, ga_b, gx_b,
            cv, a_param, TOKENS, H_DIM, H_DIM, H_DIM);
    }

    scan_mult_kernel<<<32, 128>>>(abuf, bbuf, left, lhh);

    launch_gemm<0, 0, true>(lhh, outWh, outWh,
                            x1, D_DIM, out_b, nullptr, 0, nullptr, x,
                            TOKENS, D_DIM, H_DIM, D_DIM, D_DIM, D_DIM);

    // ---- gated MLP sub-block ----
    rmsnorm_h_kernel<<<TOKENS, 256>>>(x1, norm2_w, x1nh, D_DIM);

    // up1|up2 dual with fused GLU -> f1gh (fp16)
    {
        dim3 grid(F_DIM / BND, TOKENS / BM);
        gemm_dual_kernel<0><<<grid, 256, GEMM_D_SMEM>>>(
            x1nh, up1Wh, up2Wh, f1gh, nullptr, nullptr, up1_b, up2_b,
            nullptr, nullptr, TOKENS, F_DIM, D_DIM, F_DIM);
    }

    launch_gemm<0, 0, true>(f1gh, downWh, downWh,
                            out, D_DIM, down_b, nullptr, 0, nullptr, x1,
                            TOKENS, D_DIM, F_DIM, D_DIM, D_DIM, D_DIM);
}

// round 7
// speedup vs baseline: 5.5703x; 1.0645x over previous
#include <cuda_runtime.h>
#include <cuda_fp16.h>
#include <mma.h>
#include <cstdint>

using namespace nvcuda;

// ============================================================================
// Problem dims (fixed by setup_inputs)
// ============================================================================
#define B_SZ    2
#define S_LEN   2048
#define D_DIM   2048
#define H_DIM   2048
#define F_DIM   6144
#define KCONV   4
#define TOKENS  (B_SZ * S_LEN)   // 4096

#define TD ((size_t)TOKENS * D_DIM)      // 8,388,608
#define TF ((size_t)TOKENS * F_DIM)      // 25,165,824
#define WH_HALVES ((size_t)5 * D_DIM * H_DIM + 3 * (size_t)D_DIM * F_DIM)
#define SCRATCH_FLOATS (6 * TD + 2 * TD + TF / 2 + (WH_HALVES + 1) / 2)
__device__ float g_scratch[SCRATCH_FLOATS];

// ============================================================================
// common helpers
// ============================================================================
__device__ __forceinline__ void cp_async16(uint32_t sdst, const void* gsrc) {
    asm volatile("cp.async.cg.shared.global [%0], [%1], 16;"
                 :: "r"(sdst), "l"(gsrc) : "memory");
}
__device__ __forceinline__ void cp_commit() {
    asm volatile("cp.async.commit_group;" ::: "memory");
}
template <int N>
__device__ __forceinline__ void cp_wait() {
    asm volatile("cp.async.wait_group %0;" :: "n"(N) : "memory");
}
__device__ __forceinline__ float gelu_f(float x) {
    return 0.5f * x * (1.0f + erff(x * 0.70710678118654752440f));
}
__device__ __forceinline__ float sigmoid_f(float x) {
    return 1.0f / (1.0f + expf(-x));
}

// ============================================================================
// Single-output fp16 GEMM (dual-B scatter by Nsplit), fused epilogue.
// Tile 128x128x64, 256 threads, 3-stage cp.async. 2 CTAs/SM (215KB smem).
// ============================================================================
#define BM 128
#define BN 128
#define BK 64
#define STAGES 3
#define LDA_S 72      // 64 + 8 pad halves; 144B rows, 16B aligned
#define LDB_S 136     // 128 + 8 pad halves
#define LDC_S 132
#define A_ST (BM * LDA_S)                     // 9216 halves
#define B_ST (BK * LDB_S)                     // 8704 halves
#define STAGE_HALVES (A_ST + B_ST)            // 17920
#define PIPE_BYTES (STAGES * STAGE_HALVES * 2)   // 107,520
#define EPI_BYTES (BM * LDC_S * 4)               // 67,584
#define GEMM_SMEM (PIPE_BYTES > EPI_BYTES ? PIPE_BYTES : EPI_BYTES)

// ACT: 0 none, 1 gelu
template <int ACT0, int ACT1, bool RES>
__global__ void __launch_bounds__(256, 2)
gemm_h_kernel(const __half* __restrict__ A,
              const __half* __restrict__ B0, const __half* __restrict__ B1,
              float* __restrict__ C0, int ldc0, const float* __restrict__ bias0,
              float* __restrict__ C1, int ldc1, const float* __restrict__ bias1,
              const float* __restrict__ res,
              int M, int K, int Nsplit, int ldb0, int ldb1) {
    extern __shared__ __half smemh[];
    const int tid = threadIdx.x;
    const int warp = tid >> 5;
    const int bm = blockIdx.y * BM;
    const int bn = blockIdx.x * BN;

    const bool half1 = (bn >= Nsplit);
    const __half* Bsel = half1 ? B1 : B0;
    const int ldb = half1 ? ldb1 : ldb0;
    const int cb = bn - (half1 ? Nsplit : 0);

    const int wm = (warp >> 1) * 32;
    const int wn = (warp & 1) * 64;

    wmma::fragment<wmma::accumulator, 16, 16, 16, float> acc[2][4];
    #pragma unroll
    for (int mi = 0; mi < 2; mi++)
        #pragma unroll
        for (int ni = 0; ni < 4; ni++)
            wmma::fill_fragment(acc[mi][ni], 0.0f);

    const uint32_t smem_u32 = (uint32_t)__cvta_generic_to_shared(smemh);
    const int nk = K / BK;
    const __half* Abase = A + (size_t)bm * K;
    const __half* Bbase = Bsel + cb;

    auto issue_stage = [&](int s, int kc) {
        const uint32_t sA = smem_u32 + (uint32_t)(s * STAGE_HALVES) * 2u;
        const uint32_t sB = sA + (uint32_t)A_ST * 2u;
        const __half* Ab = Abase + (size_t)kc * BK;
        const __half* Bb = Bbase + (size_t)kc * BK * ldb;
        #pragma unroll
        for (int p = 0; p < 4; p++) {       // A: 128 rows x 8 chunks(8h)
            int id = p * 256 + tid;
            int r = id >> 3, c = id & 7;
            cp_async16(sA + (uint32_t)(r * LDA_S + c * 8) * 2u,
                       Ab + (size_t)r * K + c * 8);
        }
        #pragma unroll
        for (int p = 0; p < 4; p++) {       // B: 64 rows x 16 chunks
            int id = p * 256 + tid;
            int r = id >> 4, c = id & 15;
            cp_async16(sB + (uint32_t)(r * LDB_S + c * 8) * 2u,
                       Bb + (size_t)r * ldb + c * 8);
        }
    };

    #pragma unroll
    for (int s = 0; s < STAGES - 1; s++) { issue_stage(s, s); cp_commit(); }

    int cur = 0;
    for (int kc = 0; kc < nk; kc++) {
        cp_wait<STAGES - 2>();
        __syncthreads();
        int pf = kc + STAGES - 1;
        if (pf < nk) {
            int s = cur + STAGES - 1;
            if (s >= STAGES) s -= STAGES;
            issue_stage(s, pf);
        }
        cp_commit();

        const __half* sA = smemh + cur * STAGE_HALVES;
        const __half* sB = sA + A_ST;
        #pragma unroll
        for (int kk = 0; kk < BK; kk += 16) {
            wmma::fragment<wmma::matrix_b, 16, 16, 16, __half,
                           wmma::row_major> bf[4];
            #pragma unroll
            for (int ni = 0; ni < 4; ni++)
                wmma::load_matrix_sync(bf[ni], sB + kk * LDB_S + wn + ni * 16,
                                       LDB_S);
            #pragma unroll
            for (int mi = 0; mi < 2; mi++) {
                wmma::fragment<wmma::matrix_a, 16, 16, 16, __half,
                               wmma::row_major> af;
                wmma::load_matrix_sync(af, sA + (wm + mi * 16) * LDA_S + kk,
                                       LDA_S);
                #pragma unroll
                for (int ni = 0; ni < 4; ni++)
                    wmma::mma_sync(acc[mi][ni], af, bf[ni], acc[mi][ni]);
            }
        }
        cur = (cur + 1 == STAGES) ? 0 : cur + 1;
    }

    cp_wait<0>();
    __syncthreads();
    float* Cs = reinterpret_cast<float*>(smemh);
    #pragma unroll
    for (int mi = 0; mi < 2; mi++)
        #pragma unroll
        for (int ni = 0; ni < 4; ni++)
            wmma::store_matrix_sync(Cs + (wm + mi * 16) * LDC_S + wn + ni * 16,
                                    acc[mi][ni], LDC_S, wmma::mem_row_major);
    __syncthreads();

    float* Cout = half1 ? C1 : C0;
    const int ldc = half1 ? ldc1 : ldc0;
    const float* bias = half1 ? bias1 : bias0;
    const int act = half1 ? ACT1 : ACT0;

    const int r = tid >> 1;
    const int cseg = (tid & 1) * 64;
    const size_t grow = (size_t)(bm + r);
    float* gout = Cout + grow * ldc + cb + cseg;
    const float* biasp = bias + cb + cseg;
    const float* resp = RES ? (res + grow * ldc0 + cb + cseg) : nullptr;
    const float* csrow = Cs + r * LDC_S + cseg;

    #pragma unroll
    for (int j = 0; j < 16; j++) {
        float4 v = *(const float4*)(csrow + j * 4);
        float4 b = *(const float4*)(biasp + j * 4);
        v.x += b.x; v.y += b.y; v.z += b.z; v.w += b.w;
        if (act == 1) {
            v.x = gelu_f(v.x); v.y = gelu_f(v.y);
            v.z = gelu_f(v.z); v.w = gelu_f(v.w);
        }
        if (RES) {
            float4 rv = *(const float4*)(resp + j * 4);
            v.x += rv.x; v.y += rv.y; v.z += rv.z; v.w += rv.w;
        }
        *(float4*)(gout + j * 4) = v;
    }
}

// ============================================================================
// Dual-accumulator GEMM (same N cols of A@B0 and A@B1, combined epilogue).
// Tile 128 x 64(x2) x 64, 256 threads, 3-stage cp.async.
// COMBINE 0 (GLU): out0h = half( gelu(v0+b0) * (v1+b1) )
// COMBINE 1 (AB):  a=exp(-8*softplus(ap)*sig(v0+b0));
//                  b=sqrt(-expm1(2la))*sig(v1+b1)*xc
// ============================================================================
#define BND 64
#define LDBD 72
#define B_STD (BK * LDBD)                       // 4608 halves
#define STAGE_D (A_ST + 2 * B_STD)              // 18432 halves
#define PIPE_D_BYTES (STAGES * STAGE_D * 2)     // 110,592
#define LDC_D 68
#define EPI_D_BYTES (2 * BM * LDC_D * 4)        // 69,632
#define GEMM_D_SMEM (PIPE_D_BYTES > EPI_D_BYTES ? PIPE_D_BYTES : EPI_D_BYTES)

template <int COMBINE>
__global__ void __launch_bounds__(256, 2)
gemm_dual_kernel(const __half* __restrict__ A,
                 const __half* __restrict__ B0, const __half* __restrict__ B1,
                 __half* __restrict__ out0h,
                 float* __restrict__ out0f, float* __restrict__ out1f,
                 const float* __restrict__ bias0,
                 const float* __restrict__ bias1,
                 const float* __restrict__ xc, const float* __restrict__ ap,
                 int M, int N, int K, int ldb) {
    extern __shared__ __half smemh[];
    const int tid = threadIdx.x;
    const int warp = tid >> 5;
    const int bm = blockIdx.y * BM;
    const int bn = blockIdx.x * BND;

    const int wm = (warp >> 1) * 32;
    const int wn = (warp & 1) * 32;

    wmma::fragment<wmma::accumulator, 16, 16, 16, float> acc0[2][2], acc1[2][2];
    #pragma unroll
    for (int mi = 0; mi < 2; mi++)
        #pragma unroll
        for (int ni = 0; ni < 2; ni++) {
            wmma::fill_fragment(acc0[mi][ni], 0.0f);
            wmma::fill_fragment(acc1[mi][ni], 0.0f);
        }

    const uint32_t smem_u32 = (uint32_t)__cvta_generic_to_shared(smemh);
    const int nk = K / BK;
    const __half* Abase = A + (size_t)bm * K;
    const __half* B0base = B0 + bn;
    const __half* B1base = B1 + bn;

    auto issue_stage = [&](int s, int kc) {
        const uint32_t sA = smem_u32 + (uint32_t)(s * STAGE_D) * 2u;
        const uint32_t sB0 = sA + (uint32_t)A_ST * 2u;
        const uint32_t sB1 = sB0 + (uint32_t)B_STD * 2u;
        const __half* Ab = Abase + (size_t)kc * BK;
        const size_t brow = (size_t)kc * BK * ldb;
        #pragma unroll
        for (int p = 0; p < 4; p++) {       // A: 128 rows x 8 chunks
            int id = p * 256 + tid;
            int r = id >> 3, c = id & 7;
            cp_async16(sA + (uint32_t)(r * LDA_S + c * 8) * 2u,
                       Ab + (size_t)r * K + c * 8);
        }
        #pragma unroll
        for (int p = 0; p < 2; p++) {       // B0,B1: 64 rows x 8 chunks each
            int id = p * 256 + tid;
            int r = id >> 3, c = id & 7;
            cp_async16(sB0 + (uint32_t)(r * LDBD + c * 8) * 2u,
                       B0base + brow + (size_t)r * ldb + c * 8);
            cp_async16(sB1 + (uint32_t)(r * LDBD + c * 8) * 2u,
                       B1base + brow + (size_t)r * ldb + c * 8);
        }
    };

    #pragma unroll
    for (int s = 0; s < STAGES - 1; s++) { issue_stage(s, s); cp_commit(); }

    int cur = 0;
    for (int kc = 0; kc < nk; kc++) {
        cp_wait<STAGES - 2>();
        __syncthreads();
        int pf = kc + STAGES - 1;
        if (pf < nk) {
            int s = cur + STAGES - 1;
            if (s >= STAGES) s -= STAGES;
            issue_stage(s, pf);
        }
        cp_commit();

        const __half* sA = smemh + cur * STAGE_D;
        const __half* sB0 = sA + A_ST;
        const __half* sB1 = sB0 + B_STD;
        #pragma unroll
        for (int kk = 0; kk < BK; kk += 16) {
            wmma::fragment<wmma::matrix_b, 16, 16, 16, __half,
                           wmma::row_major> b0f[2], b1f[2];
            #pragma unroll
            for (int ni = 0; ni < 2; ni++) {
                wmma::load_matrix_sync(b0f[ni], sB0 + kk * LDBD + wn + ni * 16,
                                       LDBD);
                wmma::load_matrix_sync(b1f[ni], sB1 + kk * LDBD + wn + ni * 16,
                                       LDBD);
            }
            #pragma unroll
            for (int mi = 0; mi < 2; mi++) {
                wmma::fragment<wmma::matrix_a, 16, 16, 16, __half,
                               wmma::row_major> af;
                wmma::load_matrix_sync(af, sA + (wm + mi * 16) * LDA_S + kk,
                                       LDA_S);
                #pragma unroll
                for (int ni = 0; ni < 2; ni++) {
                    wmma::mma_sync(acc0[mi][ni], af, b0f[ni], acc0[mi][ni]);
                    wmma::mma_sync(acc1[mi][ni], af, b1f[ni], acc1[mi][ni]);
                }
            }
        }
        cur = (cur + 1 == STAGES) ? 0 : cur + 1;
    }

    cp_wait<0>();
    __syncthreads();
    float* Cs0 = reinterpret_cast<float*>(smemh);
    float* Cs1 = Cs0 + BM * LDC_D;
    #pragma unroll
    for (int mi = 0; mi < 2; mi++)
        #pragma unroll
        for (int ni = 0; ni < 2; ni++) {
            wmma::store_matrix_sync(Cs0 + (wm + mi * 16) * LDC_D + wn + ni * 16,
                                    acc0[mi][ni], LDC_D, wmma::mem_row_major);
            wmma::store_matrix_sync(Cs1 + (wm + mi * 16) * LDC_D + wn + ni * 16,
                                    acc1[mi][ni], LDC_D, wmma::mem_row_major);
        }
    __syncthreads();

    const int r = tid >> 1;
    const int c0 = (tid & 1) * 32;
    const size_t row = (size_t)(bm + r);
    const int gcol = bn + c0;

    #pragma unroll
    for (int j = 0; j < 8; j++) {
        const int cc = c0 + j * 4;
        float4 v0 = *(const float4*)(Cs0 + r * LDC_D + cc);
        float4 v1 = *(const float4*)(Cs1 + r * LDC_D + cc);
        float4 b0 = *(const float4*)(bias0 + gcol + j * 4);
        float4 b1 = *(const float4*)(bias1 + gcol + j * 4);
        v0.x += b0.x; v0.y += b0.y; v0.z += b0.z; v0.w += b0.w;
        v1.x += b1.x; v1.y += b1.y; v1.z += b1.z; v1.w += b1.w;
        if (COMBINE == 0) {
            float4 p;
            p.x = gelu_f(v0.x) * v1.x;
            p.y = gelu_f(v0.y) * v1.y;
            p.z = gelu_f(v0.z) * v1.z;
            p.w = gelu_f(v0.w) * v1.w;
            __half2* dst = (__half2*)(out0h + row * N + gcol + j * 4);
            dst[0] = __floats2half2_rn(p.x, p.y);
            dst[1] = __floats2half2_rn(p.z, p.w);
        } else {
            float4 apv = *(const float4*)(ap + gcol + j * 4);
            float4 xcv = *(const float4*)(xc + row * N + gcol + j * 4);
            float4 av, bv;
            {
                float rr = sigmoid_f(v0.x), ii = sigmoid_f(v1.x);
                float la = -8.0f * log1pf(expf(apv.x)) * rr;
                av.x = expf(la);
                bv.x = sqrtf(-expm1f(2.0f * la)) * ii * xcv.x;
            }
            {
                float rr = sigmoid_f(v0.y), ii = sigmoid_f(v1.y);
                float la = -8.0f * log1pf(expf(apv.y)) * rr;
                av.y = expf(la);
                bv.y = sqrtf(-expm1f(2.0f * la)) * ii * xcv.y;
            }
            {
                float rr = sigmoid_f(v0.z), ii = sigmoid_f(v1.z);
                float la = -8.0f * log1pf(expf(apv.z)) * rr;
                av.z = expf(la);
                bv.z = sqrtf(-expm1f(2.0f * la)) * ii * xcv.z;
            }
            {
                float rr = sigmoid_f(v0.w), ii = sigmoid_f(v1.w);
                float la = -8.0f * log1pf(expf(apv.w)) * rr;
                av.w = expf(la);
                bv.w = sqrtf(-expm1f(2.0f * la)) * ii * xcv.w;
            }
            *(float4*)(out0f + row * N + gcol + j * 4) = av;
            *(float4*)(out1f + row * N + gcol + j * 4) = bv;
        }
    }
}

// ============================================================================
// Fused fp32->fp16 weight conversion: one launch, 8 segments, vectorized.
// ============================================================================
struct F2HSeg { const float* src; __half* dst; size_t n4; };  // n4 = n/4
struct F2HArgs { F2HSeg seg[8]; };

__global__ void f2h_all_kernel(F2HArgs args) {
    for (int s = 0; s < 8; s++) {
        const float4* src = (const float4*)args.seg[s].src;
        __half2* dst = (__half2*)args.seg[s].dst;
        size_t n4 = args.seg[s].n4;
        for (size_t i = (size_t)blockIdx.x * blockDim.x + threadIdx.x; i < n4;
             i += (size_t)gridDim.x * blockDim.x) {
            float4 v = src[i];
            dst[i * 2 + 0] = __floats2half2_rn(v.x, v.y);
            dst[i * 2 + 1] = __floats2half2_rn(v.z, v.w);
        }
    }
}

// ============================================================================
// Elementwise kernels
// ============================================================================
__global__ void rmsnorm_h_kernel(const float* __restrict__ x,
                                 const float* __restrict__ w,
                                 __half* __restrict__ out, int D) {
    const float* row = x + (size_t)blockIdx.x * D;
    __half* orow = out + (size_t)blockIdx.x * D;
    float s = 0.0f;
    for (int i = threadIdx.x; i < D; i += blockDim.x) {
        float v = row[i];
        s += v * v;
    }
    #pragma unroll
    for (int off = 16; off > 0; off >>= 1)
        s += __shfl_xor_sync(0xFFFFFFFF, s, off);
    __shared__ float red[32];
    int lane = threadIdx.x & 31, warp = threadIdx.x >> 5;
    if (lane == 0) red[warp] = s;
    __syncthreads();
    int nwarps = blockDim.x >> 5;
    if (warp == 0) {
        float t = (lane < nwarps) ? red[lane] : 0.0f;
        #pragma unroll
        for (int off = 16; off > 0; off >>= 1)
            t += __shfl_xor_sync(0xFFFFFFFF, t, off);
        if (lane == 0) red[0] = t;
    }
    __syncthreads();
    float inv = rsqrtf(red[0] / (float)D + 1e-8f);
    for (int i = threadIdx.x; i < D; i += blockDim.x)
        orow[i] = __float2half(w[i] * row[i] * inv);
}

__global__ void conv_kernel(const float* __restrict__ x,
                            const float* __restrict__ w,
                            const float* __restrict__ bias,
                            float* __restrict__ y,
                            __half* __restrict__ yh) {
    const size_t total = (size_t)TOKENS * H_DIM;
    for (size_t i = (size_t)blockIdx.x * blockDim.x + threadIdx.x; i < total;
         i += (size_t)gridDim.x * blockDim.x) {
        int h = (int)(i % H_DIM);
        int t = (int)((i / H_DIM) % S_LEN);
        float acc = bias[h];
        #pragma unroll
        for (int k = 0; k < KCONV; k++) {
            int tt = t - (KCONV - 1) + k;
            if (tt >= 0)
                acc += w[k * H_DIM + h] * x[i + (size_t)(tt - t) * H_DIM];
        }
        y[i] = acc;
        yh[i] = __float2half(acc);
    }
}

// fused scan + gate-multiply: h_t = a_t h_{t-1} + b_t;  lh = half(left * h)
__global__ void scan_mult_kernel(const float* __restrict__ a,
                                 const float* __restrict__ b,
                                 const float* __restrict__ left,
                                 __half* __restrict__ lh) {
    int idx = blockIdx.x * blockDim.x + threadIdx.x;
    if (idx >= B_SZ * H_DIM) return;
    int bb = idx / H_DIM;
    int hh = idx % H_DIM;
    size_t base = (size_t)bb * S_LEN * H_DIM + hh;
    float state = 0.0f;
    #pragma unroll 4
    for (int t = 0; t < S_LEN; t++) {
        size_t o = base + (size_t)t * H_DIM;
        state = fmaf(a[o], state, b[o]);
        lh[o] = __float2half(left[o] * state);
    }
}

// ============================================================================
// Host launch
// ============================================================================
template <int ACT0, int ACT1, bool RES>
static inline void launch_gemm(const __half* A,
                               const __half* B0, const __half* B1,
                               float* C0, int ldc0, const float* bias0,
                               float* C1, int ldc1, const float* bias1,
                               const float* res,
                               int M, int Ntot, int K, int Nsplit,
                               int ldb0, int ldb1) {
    dim3 grid(Ntot / BN, M / BM);
    gemm_h_kernel<ACT0, ACT1, RES><<<grid, 256, GEMM_SMEM>>>(
        A, B0, B1, C0, ldc0, bias0, C1, ldc1, bias1, res,
        M, K, Nsplit, ldb0, ldb1);
}

extern "C" void kernel_launch(void* const* d_in, const int* in_sizes, int n_in,
                              void* d_out, int out_size) {
    (void)in_sizes; (void)n_in; (void)out_size;
    const float* x       = (const float*)d_in[0];
    const float* norm1_w = (const float*)d_in[1];
    const float* left_W  = (const float*)d_in[2];
    const float* left_b  = (const float*)d_in[3];
    const float* right_W = (const float*)d_in[4];
    const float* right_b = (const float*)d_in[5];
    const float* conv_w  = (const float*)d_in[6];
    const float* conv_b  = (const float*)d_in[7];
    const float* ga_W    = (const float*)d_in[8];
    const float* ga_b    = (const float*)d_in[9];
    const float* gx_W    = (const float*)d_in[10];
    const float* gx_b    = (const float*)d_in[11];
    const float* a_param = (const float*)d_in[12];
    const float* out_W   = (const float*)d_in[13];
    const float* out_b   = (const float*)d_in[14];
    const float* norm2_w = (const float*)d_in[15];
    const float* up1_W   = (const float*)d_in[16];
    const float* up1_b   = (const float*)d_in[17];
    const float* up2_W   = (const float*)d_in[18];
    const float* up2_b   = (const float*)d_in[19];
    const float* down_W  = (const float*)d_in[20];
    const float* down_b  = (const float*)d_in[21];
    float* out = (float*)d_out;

    cudaFuncSetAttribute(gemm_h_kernel<1, 0, false>,
                         cudaFuncAttributeMaxDynamicSharedMemorySize, GEMM_SMEM);
    cudaFuncSetAttribute(gemm_h_kernel<0, 0, true>,
                         cudaFuncAttributeMaxDynamicSharedMemorySize, GEMM_SMEM);
    cudaFuncSetAttribute(gemm_dual_kernel<0>,
                         cudaFuncAttributeMaxDynamicSharedMemorySize, GEMM_D_SMEM);
    cudaFuncSetAttribute(gemm_dual_kernel<1>,
                         cudaFuncAttributeMaxDynamicSharedMemorySize, GEMM_D_SMEM);

    float* scratch = nullptr;
    cudaGetSymbolAddress((void**)&scratch, g_scratch);
    float* left = scratch;          // [TOKENS, H]
    float* rp   = left + TD;        // [TOKENS, H]
    float* cv   = rp + TD;          // [TOKENS, H]
    float* abuf = cv + TD;          // [TOKENS, H]
    float* bbuf = abuf + TD;        // [TOKENS, H]
    float* x1   = bbuf + TD;        // [TOKENS, D]
    __half* xnh  = (__half*)(x1 + TD);          // [TOKENS, D]
    __half* cvh  = xnh + TD;                    // [TOKENS, H]
    __half* lhh  = cvh + TD;                    // [TOKENS, H]
    __half* x1nh = lhh + TD;                    // [TOKENS, D]
    __half* f1gh = x1nh + TD;                   // [TOKENS, F]
    __half* wh   = f1gh + TF;
    __half* leftWh  = wh;
    __half* rightWh = leftWh  + (size_t)D_DIM * H_DIM;
    __half* gaWh    = rightWh + (size_t)D_DIM * H_DIM;
    __half* gxWh    = gaWh    + (size_t)H_DIM * H_DIM;
    __half* outWh   = gxWh    + (size_t)H_DIM * H_DIM;
    __half* up1Wh   = outWh   + (size_t)H_DIM * D_DIM;
    __half* up2Wh   = up1Wh   + (size_t)D_DIM * F_DIM;
    __half* downWh  = up2Wh   + (size_t)D_DIM * F_DIM;

    const int EPI_BLOCKS = 2048;

    // ---- fused weight conversion (single launch, vectorized) ----
    {
        F2HArgs fa;
        fa.seg[0] = { left_W,  leftWh,  (size_t)D_DIM * H_DIM / 4 };
        fa.seg[1] = { right_W, rightWh, (size_t)D_DIM * H_DIM / 4 };
        fa.seg[2] = { ga_W,    gaWh,    (size_t)H_DIM * H_DIM / 4 };
        fa.seg[3] = { gx_W,    gxWh,    (size_t)H_DIM * H_DIM / 4 };
        fa.seg[4] = { out_W,   outWh,   (size_t)H_DIM * D_DIM / 4 };
        fa.seg[5] = { up1_W,   up1Wh,   (size_t)D_DIM * F_DIM / 4 };
        fa.seg[6] = { up2_W,   up2Wh,   (size_t)D_DIM * F_DIM / 4 };
        fa.seg[7] = { down_W,  downWh,  (size_t)F_DIM * D_DIM / 4 };
        f2h_all_kernel<<<2368, 256>>>(fa);
    }

    // ---- recurrent sub-block ----
    rmsnorm_h_kernel<<<TOKENS, 256>>>(x, norm1_w, xnh, D_DIM);

    launch_gemm<1, 0, false>(xnh, leftWh, rightWh,
                             left, H_DIM, left_b, rp, H_DIM, right_b, nullptr,
                             TOKENS, 2 * H_DIM, D_DIM, H_DIM, H_DIM, H_DIM);

    conv_kernel<<<EPI_BLOCKS, 256>>>(rp, conv_w, conv_b, cv, cvh);

    {
        dim3 grid(H_DIM / BND, TOKENS / BM);
        gemm_dual_kernel<1><<<grid, 256, GEMM_D_SMEM>>>(
            cvh, gaWh, gxWh, nullptr, abuf, bbuf, ga_b, gx_b,
            cv, a_param, TOKENS, H_DIM, H_DIM, H_DIM);
    }

    scan_mult_kernel<<<32, 128>>>(abuf, bbuf, left, lhh);

    launch_gemm<0, 0, true>(lhh, outWh, outWh,
                            x1, D_DIM, out_b, nullptr, 0, nullptr, x,
                            TOKENS, D_DIM, H_DIM, D_DIM, D_DIM, D_DIM);

    // ---- gated MLP sub-block ----
    rmsnorm_h_kernel<<<TOKENS, 256>>>(x1, norm2_w, x1nh, D_DIM);

    {
        dim3 grid(F_DIM / BND, TOKENS / BM);
        gemm_dual_kernel<0><<<grid, 256, GEMM_D_SMEM>>>(
            x1nh, up1Wh, up2Wh, f1gh, nullptr, nullptr, up1_b, up2_b,
            nullptr, nullptr, TOKENS, F_DIM, D_DIM, F_DIM);
    }

    launch_gemm<0, 0, true>(f1gh, downWh, downWh,
                            out, D_DIM, down_b, nullptr, 0, nullptr, x1,
                            TOKENS, D_DIM, F_DIM, D_DIM, D_DIM, D_DIM);
}

// round 8
// speedup vs baseline: 6.4555x; 1.1589x over previous
#include <cuda_runtime.h>
#include <cuda_fp16.h>
#include <mma.h>
#include <cstdint>

using namespace nvcuda;

// ============================================================================
// Problem dims (fixed by setup_inputs)
// ============================================================================
#define B_SZ    2
#define S_LEN   2048
#define D_DIM   2048
#define H_DIM   2048
#define F_DIM   6144
#define KCONV   4
#define TOKENS  (B_SZ * S_LEN)   // 4096

#define TD ((size_t)TOKENS * D_DIM)      // 8,388,608
#define TF ((size_t)TOKENS * F_DIM)      // 25,165,824
#define WH_HALVES ((size_t)5 * D_DIM * H_DIM + 3 * (size_t)D_DIM * F_DIM)
// chunked-scan summaries: 3 * B*NCH*H floats
#define NCH 16
#define CHL (S_LEN / NCH)                 // 128
#define SCAN_FLOATS ((size_t)3 * B_SZ * NCH * H_DIM)
#define SCRATCH_FLOATS (6 * TD + 2 * TD + TF / 2 + (WH_HALVES + 1) / 2 + SCAN_FLOATS)
__device__ float g_scratch[SCRATCH_FLOATS];

// ============================================================================
// common helpers
// ============================================================================
__device__ __forceinline__ void cp_async16(uint32_t sdst, const void* gsrc) {
    asm volatile("cp.async.cg.shared.global [%0], [%1], 16;"
                 :: "r"(sdst), "l"(gsrc) : "memory");
}
__device__ __forceinline__ void cp_commit() {
    asm volatile("cp.async.commit_group;" ::: "memory");
}
template <int N>
__device__ __forceinline__ void cp_wait() {
    asm volatile("cp.async.wait_group %0;" :: "n"(N) : "memory");
}
__device__ __forceinline__ float gelu_f(float x) {
    return 0.5f * x * (1.0f + erff(x * 0.70710678118654752440f));
}
__device__ __forceinline__ float sigmoid_f(float x) {
    return 1.0f / (1.0f + expf(-x));
}

// ============================================================================
// Single-output fp16 GEMM (dual-B scatter by Nsplit), fused epilogue.
// Tile 128x128x64, 256 threads, 3-stage cp.async. 2 CTAs/SM.
// ============================================================================
#define BM 128
#define BN 128
#define BK 64
#define STAGES 3
#define LDA_S 72
#define LDB_S 136
#define LDC_S 132
#define A_ST (BM * LDA_S)                     // 9216 halves
#define B_ST (BK * LDB_S)                     // 8704 halves
#define STAGE_HALVES (A_ST + B_ST)            // 17920
#define PIPE_BYTES (STAGES * STAGE_HALVES * 2)   // 107,520
#define EPI_BYTES (BM * LDC_S * 4)               // 67,584
#define GEMM_SMEM (PIPE_BYTES > EPI_BYTES ? PIPE_BYTES : EPI_BYTES)

// ACT: 0 none, 1 gelu
template <int ACT0, int ACT1, bool RES>
__global__ void __launch_bounds__(256, 2)
gemm_h_kernel(const __half* __restrict__ A,
              const __half* __restrict__ B0, const __half* __restrict__ B1,
              float* __restrict__ C0, int ldc0, const float* __restrict__ bias0,
              float* __restrict__ C1, int ldc1, const float* __restrict__ bias1,
              const float* __restrict__ res,
              int M, int K, int Nsplit, int ldb0, int ldb1) {
    extern __shared__ __half smemh[];
    const int tid = threadIdx.x;
    const int warp = tid >> 5;
    const int bm = blockIdx.y * BM;
    const int bn = blockIdx.x * BN;

    const bool half1 = (bn >= Nsplit);
    const __half* Bsel = half1 ? B1 : B0;
    const int ldb = half1 ? ldb1 : ldb0;
    const int cb = bn - (half1 ? Nsplit : 0);

    const int wm = (warp >> 1) * 32;
    const int wn = (warp & 1) * 64;

    wmma::fragment<wmma::accumulator, 16, 16, 16, float> acc[2][4];
    #pragma unroll
    for (int mi = 0; mi < 2; mi++)
        #pragma unroll
        for (int ni = 0; ni < 4; ni++)
            wmma::fill_fragment(acc[mi][ni], 0.0f);

    const uint32_t smem_u32 = (uint32_t)__cvta_generic_to_shared(smemh);
    const int nk = K / BK;
    const __half* Abase = A + (size_t)bm * K;
    const __half* Bbase = Bsel + cb;

    auto issue_stage = [&](int s, int kc) {
        const uint32_t sA = smem_u32 + (uint32_t)(s * STAGE_HALVES) * 2u;
        const uint32_t sB = sA + (uint32_t)A_ST * 2u;
        const __half* Ab = Abase + (size_t)kc * BK;
        const __half* Bb = Bbase + (size_t)kc * BK * ldb;
        #pragma unroll
        for (int p = 0; p < 4; p++) {       // A: 128 rows x 8 chunks(8h)
            int id = p * 256 + tid;
            int r = id >> 3, c = id & 7;
            cp_async16(sA + (uint32_t)(r * LDA_S + c * 8) * 2u,
                       Ab + (size_t)r * K + c * 8);
        }
        #pragma unroll
        for (int p = 0; p < 4; p++) {       // B: 64 rows x 16 chunks
            int id = p * 256 + tid;
            int r = id >> 4, c = id & 15;
            cp_async16(sB + (uint32_t)(r * LDB_S + c * 8) * 2u,
                       Bb + (size_t)r * ldb + c * 8);
        }
    };

    #pragma unroll
    for (int s = 0; s < STAGES - 1; s++) { issue_stage(s, s); cp_commit(); }

    int cur = 0;
    for (int kc = 0; kc < nk; kc++) {
        cp_wait<STAGES - 2>();
        __syncthreads();
        int pf = kc + STAGES - 1;
        if (pf < nk) {
            int s = cur + STAGES - 1;
            if (s >= STAGES) s -= STAGES;
            issue_stage(s, pf);
        }
        cp_commit();

        const __half* sA = smemh + cur * STAGE_HALVES;
        const __half* sB = sA + A_ST;
        #pragma unroll
        for (int kk = 0; kk < BK; kk += 16) {
            wmma::fragment<wmma::matrix_b, 16, 16, 16, __half,
                           wmma::row_major> bf[4];
            #pragma unroll
            for (int ni = 0; ni < 4; ni++)
                wmma::load_matrix_sync(bf[ni], sB + kk * LDB_S + wn + ni * 16,
                                       LDB_S);
            #pragma unroll
            for (int mi = 0; mi < 2; mi++) {
                wmma::fragment<wmma::matrix_a, 16, 16, 16, __half,
                               wmma::row_major> af;
                wmma::load_matrix_sync(af, sA + (wm + mi * 16) * LDA_S + kk,
                                       LDA_S);
                #pragma unroll
                for (int ni = 0; ni < 4; ni++)
                    wmma::mma_sync(acc[mi][ni], af, bf[ni], acc[mi][ni]);
            }
        }
        cur = (cur + 1 == STAGES) ? 0 : cur + 1;
    }

    cp_wait<0>();
    __syncthreads();
    float* Cs = reinterpret_cast<float*>(smemh);
    #pragma unroll
    for (int mi = 0; mi < 2; mi++)
        #pragma unroll
        for (int ni = 0; ni < 4; ni++)
            wmma::store_matrix_sync(Cs + (wm + mi * 16) * LDC_S + wn + ni * 16,
                                    acc[mi][ni], LDC_S, wmma::mem_row_major);
    __syncthreads();

    float* Cout = half1 ? C1 : C0;
    const int ldc = half1 ? ldc1 : ldc0;
    const float* bias = half1 ? bias1 : bias0;
    const int act = half1 ? ACT1 : ACT0;

    const int r = tid >> 1;
    const int cseg = (tid & 1) * 64;
    const size_t grow = (size_t)(bm + r);
    float* gout = Cout + grow * ldc + cb + cseg;
    const float* biasp = bias + cb + cseg;
    const float* resp = RES ? (res + grow * ldc0 + cb + cseg) : nullptr;
    const float* csrow = Cs + r * LDC_S + cseg;

    #pragma unroll
    for (int j = 0; j < 16; j++) {
        float4 v = *(const float4*)(csrow + j * 4);
        float4 b = *(const float4*)(biasp + j * 4);
        v.x += b.x; v.y += b.y; v.z += b.z; v.w += b.w;
        if (act == 1) {
            v.x = gelu_f(v.x); v.y = gelu_f(v.y);
            v.z = gelu_f(v.z); v.w = gelu_f(v.w);
        }
        if (RES) {
            float4 rv = *(const float4*)(resp + j * 4);
            v.x += rv.x; v.y += rv.y; v.z += rv.z; v.w += rv.w;
        }
        *(float4*)(gout + j * 4) = v;
    }
}

// ============================================================================
// Dual-accumulator GEMM (same N cols of A@B0 and A@B1, combined epilogue).
// Tile 128 x 64(x2) x 64, 256 threads, 3-stage cp.async.
// COMBINE 0 (GLU): out0h = half( gelu(v0+b0) * (v1+b1) )
// COMBINE 1 (AB):  a=exp(-8*softplus(ap)*sig(v0+b0));
//                  b=sqrt(-expm1(2la))*sig(v1+b1)*xc
// ============================================================================
#define BND 64
#define LDBD 72
#define B_STD (BK * LDBD)                       // 4608 halves
#define STAGE_D (A_ST + 2 * B_STD)              // 18432 halves
#define PIPE_D_BYTES (STAGES * STAGE_D * 2)     // 110,592
#define LDC_D 68
#define EPI_D_BYTES (2 * BM * LDC_D * 4)        // 69,632
#define GEMM_D_SMEM (PIPE_D_BYTES > EPI_D_BYTES ? PIPE_D_BYTES : EPI_D_BYTES)

template <int COMBINE>
__global__ void __launch_bounds__(256, 2)
gemm_dual_kernel(const __half* __restrict__ A,
                 const __half* __restrict__ B0, const __half* __restrict__ B1,
                 __half* __restrict__ out0h,
                 float* __restrict__ out0f, float* __restrict__ out1f,
                 const float* __restrict__ bias0,
                 const float* __restrict__ bias1,
                 const float* __restrict__ xc, const float* __restrict__ ap,
                 int M, int N, int K, int ldb) {
    extern __shared__ __half smemh[];
    const int tid = threadIdx.x;
    const int warp = tid >> 5;
    const int bm = blockIdx.y * BM;
    const int bn = blockIdx.x * BND;

    const int wm = (warp >> 1) * 32;
    const int wn = (warp & 1) * 32;

    wmma::fragment<wmma::accumulator, 16, 16, 16, float> acc0[2][2], acc1[2][2];
    #pragma unroll
    for (int mi = 0; mi < 2; mi++)
        #pragma unroll
        for (int ni = 0; ni < 2; ni++) {
            wmma::fill_fragment(acc0[mi][ni], 0.0f);
            wmma::fill_fragment(acc1[mi][ni], 0.0f);
        }

    const uint32_t smem_u32 = (uint32_t)__cvta_generic_to_shared(smemh);
    const int nk = K / BK;
    const __half* Abase = A + (size_t)bm * K;
    const __half* B0base = B0 + bn;
    const __half* B1base = B1 + bn;

    auto issue_stage = [&](int s, int kc) {
        const uint32_t sA = smem_u32 + (uint32_t)(s * STAGE_D) * 2u;
        const uint32_t sB0 = sA + (uint32_t)A_ST * 2u;
        const uint32_t sB1 = sB0 + (uint32_t)B_STD * 2u;
        const __half* Ab = Abase + (size_t)kc * BK;
        const size_t brow = (size_t)kc * BK * ldb;
        #pragma unroll
        for (int p = 0; p < 4; p++) {       // A: 128 rows x 8 chunks
            int id = p * 256 + tid;
            int r = id >> 3, c = id & 7;
            cp_async16(sA + (uint32_t)(r * LDA_S + c * 8) * 2u,
                       Ab + (size_t)r * K + c * 8);
        }
        #pragma unroll
        for (int p = 0; p < 2; p++) {       // B0,B1: 64 rows x 8 chunks each
            int id = p * 256 + tid;
            int r = id >> 3, c = id & 7;
            cp_async16(sB0 + (uint32_t)(r * LDBD + c * 8) * 2u,
                       B0base + brow + (size_t)r * ldb + c * 8);
            cp_async16(sB1 + (uint32_t)(r * LDBD + c * 8) * 2u,
                       B1base + brow + (size_t)r * ldb + c * 8);
        }
    };

    #pragma unroll
    for (int s = 0; s < STAGES - 1; s++) { issue_stage(s, s); cp_commit(); }

    int cur = 0;
    for (int kc = 0; kc < nk; kc++) {
        cp_wait<STAGES - 2>();
        __syncthreads();
        int pf = kc + STAGES - 1;
        if (pf < nk) {
            int s = cur + STAGES - 1;
            if (s >= STAGES) s -= STAGES;
            issue_stage(s, pf);
        }
        cp_commit();

        const __half* sA = smemh + cur * STAGE_D;
        const __half* sB0 = sA + A_ST;
        const __half* sB1 = sB0 + B_STD;
        #pragma unroll
        for (int kk = 0; kk < BK; kk += 16) {
            wmma::fragment<wmma::matrix_b, 16, 16, 16, __half,
                           wmma::row_major> b0f[2], b1f[2];
            #pragma unroll
            for (int ni = 0; ni < 2; ni++) {
                wmma::load_matrix_sync(b0f[ni], sB0 + kk * LDBD + wn + ni * 16,
                                       LDBD);
                wmma::load_matrix_sync(b1f[ni], sB1 + kk * LDBD + wn + ni * 16,
                                       LDBD);
            }
            #pragma unroll
            for (int mi = 0; mi < 2; mi++) {
                wmma::fragment<wmma::matrix_a, 16, 16, 16, __half,
                               wmma::row_major> af;
                wmma::load_matrix_sync(af, sA + (wm + mi * 16) * LDA_S + kk,
                                       LDA_S);
                #pragma unroll
                for (int ni = 0; ni < 2; ni++) {
                    wmma::mma_sync(acc0[mi][ni], af, b0f[ni], acc0[mi][ni]);
                    wmma::mma_sync(acc1[mi][ni], af, b1f[ni], acc1[mi][ni]);
                }
            }
        }
        cur = (cur + 1 == STAGES) ? 0 : cur + 1;
    }

    cp_wait<0>();
    __syncthreads();
    float* Cs0 = reinterpret_cast<float*>(smemh);
    float* Cs1 = Cs0 + BM * LDC_D;
    #pragma unroll
    for (int mi = 0; mi < 2; mi++)
        #pragma unroll
        for (int ni = 0; ni < 2; ni++) {
            wmma::store_matrix_sync(Cs0 + (wm + mi * 16) * LDC_D + wn + ni * 16,
                                    acc0[mi][ni], LDC_D, wmma::mem_row_major);
            wmma::store_matrix_sync(Cs1 + (wm + mi * 16) * LDC_D + wn + ni * 16,
                                    acc1[mi][ni], LDC_D, wmma::mem_row_major);
        }
    __syncthreads();

    const int r = tid >> 1;
    const int c0 = (tid & 1) * 32;
    const size_t row = (size_t)(bm + r);
    const int gcol = bn + c0;

    #pragma unroll
    for (int j = 0; j < 8; j++) {
        const int cc = c0 + j * 4;
        float4 v0 = *(const float4*)(Cs0 + r * LDC_D + cc);
        float4 v1 = *(const float4*)(Cs1 + r * LDC_D + cc);
        float4 b0 = *(const float4*)(bias0 + gcol + j * 4);
        float4 b1 = *(const float4*)(bias1 + gcol + j * 4);
        v0.x += b0.x; v0.y += b0.y; v0.z += b0.z; v0.w += b0.w;
        v1.x += b1.x; v1.y += b1.y; v1.z += b1.z; v1.w += b1.w;
        if (COMBINE == 0) {
            float4 p;
            p.x = gelu_f(v0.x) * v1.x;
            p.y = gelu_f(v0.y) * v1.y;
            p.z = gelu_f(v0.z) * v1.z;
            p.w = gelu_f(v0.w) * v1.w;
            __half2* dst = (__half2*)(out0h + row * N + gcol + j * 4);
            dst[0] = __floats2half2_rn(p.x, p.y);
            dst[1] = __floats2half2_rn(p.z, p.w);
        } else {
            float4 apv = *(const float4*)(ap + gcol + j * 4);
            float4 xcv = *(const float4*)(xc + row * N + gcol + j * 4);
            float4 av, bv;
            {
                float rr = sigmoid_f(v0.x), ii = sigmoid_f(v1.x);
                float la = -8.0f * log1pf(expf(apv.x)) * rr;
                av.x = expf(la);
                bv.x = sqrtf(-expm1f(2.0f * la)) * ii * xcv.x;
            }
            {
                float rr = sigmoid_f(v0.y), ii = sigmoid_f(v1.y);
                float la = -8.0f * log1pf(expf(apv.y)) * rr;
                av.y = expf(la);
                bv.y = sqrtf(-expm1f(2.0f * la)) * ii * xcv.y;
            }
            {
                float rr = sigmoid_f(v0.z), ii = sigmoid_f(v1.z);
                float la = -8.0f * log1pf(expf(apv.z)) * rr;
                av.z = expf(la);
                bv.z = sqrtf(-expm1f(2.0f * la)) * ii * xcv.z;
            }
            {
                float rr = sigmoid_f(v0.w), ii = sigmoid_f(v1.w);
                float la = -8.0f * log1pf(expf(apv.w)) * rr;
                av.w = expf(la);
                bv.w = sqrtf(-expm1f(2.0f * la)) * ii * xcv.w;
            }
            *(float4*)(out0f + row * N + gcol + j * 4) = av;
            *(float4*)(out1f + row * N + gcol + j * 4) = bv;
        }
    }
}

// ============================================================================
// Fused fp32->fp16 weight conversion: one launch, 8 segments, vectorized.
// ============================================================================
struct F2HSeg { const float* src; __half* dst; size_t n4; };
struct F2HArgs { F2HSeg seg[8]; };

__global__ void f2h_all_kernel(F2HArgs args) {
    for (int s = 0; s < 8; s++) {
        const float4* src = (const float4*)args.seg[s].src;
        __half2* dst = (__half2*)args.seg[s].dst;
        size_t n4 = args.seg[s].n4;
        for (size_t i = (size_t)blockIdx.x * blockDim.x + threadIdx.x; i < n4;
             i += (size_t)gridDim.x * blockDim.x) {
            float4 v = src[i];
            dst[i * 2 + 0] = __floats2half2_rn(v.x, v.y);
            dst[i * 2 + 1] = __floats2half2_rn(v.z, v.w);
        }
    }
}

// ============================================================================
// Elementwise kernels
// ============================================================================
__global__ void rmsnorm_h_kernel(const float* __restrict__ x,
                                 const float* __restrict__ w,
                                 __half* __restrict__ out, int D) {
    const float* row = x + (size_t)blockIdx.x * D;
    __half* orow = out + (size_t)blockIdx.x * D;
    float s = 0.0f;
    for (int i = threadIdx.x; i < D; i += blockDim.x) {
        float v = row[i];
        s += v * v;
    }
    #pragma unroll
    for (int off = 16; off > 0; off >>= 1)
        s += __shfl_xor_sync(0xFFFFFFFF, s, off);
    __shared__ float red[32];
    int lane = threadIdx.x & 31, warp = threadIdx.x >> 5;
    if (lane == 0) red[warp] = s;
    __syncthreads();
    int nwarps = blockDim.x >> 5;
    if (warp == 0) {
        float t = (lane < nwarps) ? red[lane] : 0.0f;
        #pragma unroll
        for (int off = 16; off > 0; off >>= 1)
            t += __shfl_xor_sync(0xFFFFFFFF, t, off);
        if (lane == 0) red[0] = t;
    }
    __syncthreads();
    float inv = rsqrtf(red[0] / (float)D + 1e-8f);
    for (int i = threadIdx.x; i < D; i += blockDim.x)
        orow[i] = __float2half(w[i] * row[i] * inv);
}

__global__ void conv_kernel(const float* __restrict__ x,
                            const float* __restrict__ w,
                            const float* __restrict__ bias,
                            float* __restrict__ y,
                            __half* __restrict__ yh) {
    const size_t total = (size_t)TOKENS * H_DIM;
    for (size_t i = (size_t)blockIdx.x * blockDim.x + threadIdx.x; i < total;
         i += (size_t)gridDim.x * blockDim.x) {
        int h = (int)(i % H_DIM);
        int t = (int)((i / H_DIM) % S_LEN);
        float acc = bias[h];
        #pragma unroll
        for (int k = 0; k < KCONV; k++) {
            int tt = t - (KCONV - 1) + k;
            if (tt >= 0)
                acc += w[k * H_DIM + h] * x[i + (size_t)(tt - t) * H_DIM];
        }
        y[i] = acc;
        yh[i] = __float2half(acc);
    }
}

// ============================================================================
// Chunked RG-LRU scan (3 phases). h_t = a_t h_{t-1} + b_t, h_{-1} = 0.
// Phase A: per (b,chunk,h) compute map composition (A = prod a, B = local scan).
// Phase B: per (b,h) combine NCH summaries -> per-chunk initial states.
// Phase C: re-scan each chunk from its initial state; lh = half(left * h).
// ============================================================================
__global__ void scan_phaseA(const float* __restrict__ a,
                            const float* __restrict__ b,
                            float* __restrict__ Asum,
                            float* __restrict__ Bsum) {
    int idx = blockIdx.x * blockDim.x + threadIdx.x;
    if (idx >= B_SZ * NCH * H_DIM) return;
    int h = idx & (H_DIM - 1);
    int c = (idx >> 11) & (NCH - 1);
    int bb = idx >> 15;
    size_t base = (size_t)bb * S_LEN * H_DIM + (size_t)c * CHL * H_DIM + h;
    float A = 1.0f, B = 0.0f;
    #pragma unroll 4
    for (int t = 0; t < CHL; t++) {
        size_t o = base + (size_t)t * H_DIM;
        float av = a[o], bv = b[o];
        B = fmaf(av, B, bv);
        A *= av;
    }
    Asum[idx] = A;
    Bsum[idx] = B;
}

__global__ void scan_phaseB(const float* __restrict__ Asum,
                            const float* __restrict__ Bsum,
                            float* __restrict__ init) {
    int idx = blockIdx.x * blockDim.x + threadIdx.x;
    if (idx >= B_SZ * H_DIM) return;
    int h = idx & (H_DIM - 1);
    int bb = idx >> 11;
    float state = 0.0f;
    #pragma unroll
    for (int c = 0; c < NCH; c++) {
        int s = (bb * NCH + c) * H_DIM + h;
        init[s] = state;
        state = fmaf(Asum[s], state, Bsum[s]);
    }
}

__global__ void scan_phaseC(const float* __restrict__ a,
                            const float* __restrict__ b,
                            const float* __restrict__ init,
                            const float* __restrict__ left,
                            __half* __restrict__ lh) {
    int idx = blockIdx.x * blockDim.x + threadIdx.x;
    if (idx >= B_SZ * NCH * H_DIM) return;
    int h = idx & (H_DIM - 1);
    int c = (idx >> 11) & (NCH - 1);
    int bb = idx >> 15;
    size_t base = (size_t)bb * S_LEN * H_DIM + (size_t)c * CHL * H_DIM + h;
    float state = init[idx];
    #pragma unroll 4
    for (int t = 0; t < CHL; t++) {
        size_t o = base + (size_t)t * H_DIM;
        state = fmaf(a[o], state, b[o]);
        lh[o] = __float2half(left[o] * state);
    }
}

// ============================================================================
// Host launch
// ============================================================================
template <int ACT0, int ACT1, bool RES>
static inline void launch_gemm(const __half* A,
                               const __half* B0, const __half* B1,
                               float* C0, int ldc0, const float* bias0,
                               float* C1, int ldc1, const float* bias1,
                               const float* res,
                               int M, int Ntot, int K, int Nsplit,
                               int ldb0, int ldb1) {
    dim3 grid(Ntot / BN, M / BM);
    gemm_h_kernel<ACT0, ACT1, RES><<<grid, 256, GEMM_SMEM>>>(
        A, B0, B1, C0, ldc0, bias0, C1, ldc1, bias1, res,
        M, K, Nsplit, ldb0, ldb1);
}

extern "C" void kernel_launch(void* const* d_in, const int* in_sizes, int n_in,
                              void* d_out, int out_size) {
    (void)in_sizes; (void)n_in; (void)out_size;
    const float* x       = (const float*)d_in[0];
    const float* norm1_w = (const float*)d_in[1];
    const float* left_W  = (const float*)d_in[2];
    const float* left_b  = (const float*)d_in[3];
    const float* right_W = (const float*)d_in[4];
    const float* right_b = (const float*)d_in[5];
    const float* conv_w  = (const float*)d_in[6];
    const float* conv_b  = (const float*)d_in[7];
    const float* ga_W    = (const float*)d_in[8];
    const float* ga_b    = (const float*)d_in[9];
    const float* gx_W    = (const float*)d_in[10];
    const float* gx_b    = (const float*)d_in[11];
    const float* a_param = (const float*)d_in[12];
    const float* out_W   = (const float*)d_in[13];
    const float* out_b   = (const float*)d_in[14];
    const float* norm2_w = (const float*)d_in[15];
    const float* up1_W   = (const float*)d_in[16];
    const float* up1_b   = (const float*)d_in[17];
    const float* up2_W   = (const float*)d_in[18];
    const float* up2_b   = (const float*)d_in[19];
    const float* down_W  = (const float*)d_in[20];
    const float* down_b  = (const float*)d_in[21];
    float* out = (float*)d_out;

    cudaFuncSetAttribute(gemm_h_kernel<1, 0, false>,
                         cudaFuncAttributeMaxDynamicSharedMemorySize, GEMM_SMEM);
    cudaFuncSetAttribute(gemm_h_kernel<0, 0, true>,
                         cudaFuncAttributeMaxDynamicSharedMemorySize, GEMM_SMEM);
    cudaFuncSetAttribute(gemm_dual_kernel<0>,
                         cudaFuncAttributeMaxDynamicSharedMemorySize, GEMM_D_SMEM);
    cudaFuncSetAttribute(gemm_dual_kernel<1>,
                         cudaFuncAttributeMaxDynamicSharedMemorySize, GEMM_D_SMEM);

    float* scratch = nullptr;
    cudaGetSymbolAddress((void**)&scratch, g_scratch);
    float* left = scratch;          // [TOKENS, H]
    float* rp   = left + TD;        // [TOKENS, H]
    float* cv   = rp + TD;          // [TOKENS, H]
    float* abuf = cv + TD;          // [TOKENS, H]
    float* bbuf = abuf + TD;        // [TOKENS, H]
    float* x1   = bbuf + TD;        // [TOKENS, D]
    __half* xnh  = (__half*)(x1 + TD);          // [TOKENS, D]
    __half* cvh  = xnh + TD;                    // [TOKENS, H]
    __half* lhh  = cvh + TD;                    // [TOKENS, H]
    __half* x1nh = lhh + TD;                    // [TOKENS, D]
    __half* f1gh = x1nh + TD;                   // [TOKENS, F]
    __half* wh   = f1gh + TF;
    __half* leftWh  = wh;
    __half* rightWh = leftWh  + (size_t)D_DIM * H_DIM;
    __half* gaWh    = rightWh + (size_t)D_DIM * H_DIM;
    __half* gxWh    = gaWh    + (size_t)H_DIM * H_DIM;
    __half* outWh   = gxWh    + (size_t)H_DIM * H_DIM;
    __half* up1Wh   = outWh   + (size_t)H_DIM * D_DIM;
    __half* up2Wh   = up1Wh   + (size_t)D_DIM * F_DIM;
    __half* downWh  = up2Wh   + (size_t)D_DIM * F_DIM;
    float* Asum = (float*)(downWh + (size_t)F_DIM * D_DIM);  // [B*NCH*H]
    float* Bsum = Asum + (size_t)B_SZ * NCH * H_DIM;
    float* init = Bsum + (size_t)B_SZ * NCH * H_DIM;

    const int EPI_BLOCKS = 2048;

    // ---- fused weight conversion (single launch, vectorized) ----
    {
        F2HArgs fa;
        fa.seg[0] = { left_W,  leftWh,  (size_t)D_DIM * H_DIM / 4 };
        fa.seg[1] = { right_W, rightWh, (size_t)D_DIM * H_DIM / 4 };
        fa.seg[2] = { ga_W,    gaWh,    (size_t)H_DIM * H_DIM / 4 };
        fa.seg[3] = { gx_W,    gxWh,    (size_t)H_DIM * H_DIM / 4 };
        fa.seg[4] = { out_W,   outWh,   (size_t)H_DIM * D_DIM / 4 };
        fa.seg[5] = { up1_W,   up1Wh,   (size_t)D_DIM * F_DIM / 4 };
        fa.seg[6] = { up2_W,   up2Wh,   (size_t)D_DIM * F_DIM / 4 };
        fa.seg[7] = { down_W,  downWh,  (size_t)F_DIM * D_DIM / 4 };
        f2h_all_kernel<<<2368, 256>>>(fa);
    }

    // ---- recurrent sub-block ----
    rmsnorm_h_kernel<<<TOKENS, 256>>>(x, norm1_w, xnh, D_DIM);

    launch_gemm<1, 0, false>(xnh, leftWh, rightWh,
                             left, H_DIM, left_b, rp, H_DIM, right_b, nullptr,
                             TOKENS, 2 * H_DIM, D_DIM, H_DIM, H_DIM, H_DIM);

    conv_kernel<<<EPI_BLOCKS, 256>>>(rp, conv_w, conv_b, cv, cvh);

    {
        dim3 grid(H_DIM / BND, TOKENS / BM);
        gemm_dual_kernel<1><<<grid, 256, GEMM_D_SMEM>>>(
            cvh, gaWh, gxWh, nullptr, abuf, bbuf, ga_b, gx_b,
            cv, a_param, TOKENS, H_DIM, H_DIM, H_DIM);
    }

    // chunked scan: 3 phases
    {
        const int totalA = B_SZ * NCH * H_DIM;    // 65536
        scan_phaseA<<<totalA / 256, 256>>>(abuf, bbuf, Asum, Bsum);
        scan_phaseB<<<(B_SZ * H_DIM) / 256, 256>>>(Asum, Bsum, init);
        scan_phaseC<<<totalA / 256, 256>>>(abuf, bbuf, init, left, lhh);
    }

    launch_gemm<0, 0, true>(lhh, outWh, outWh,
                            x1, D_DIM, out_b, nullptr, 0, nullptr, x,
                            TOKENS, D_DIM, H_DIM, D_DIM, D_DIM, D_DIM);

    // ---- gated MLP sub-block ----
    rmsnorm_h_kernel<<<TOKENS, 256>>>(x1, norm2_w, x1nh, D_DIM);

    {
        dim3 grid(F_DIM / BND, TOKENS / BM);
        gemm_dual_kernel<0><<<grid, 256, GEMM_D_SMEM>>>(
            x1nh, up1Wh, up2Wh, f1gh, nullptr, nullptr, up1_b, up2_b,
            nullptr, nullptr, TOKENS, F_DIM, D_DIM, F_DIM);
    }

    launch_gemm<0, 0, true>(f1gh, downWh, downWh,
                            out, D_DIM, down_b, nullptr, 0, nullptr, x1,
                            TOKENS, D_DIM, F_DIM, D_DIM, D_DIM, D_DIM);
}

// round 9
// speedup vs baseline: 6.5390x; 1.0129x over previous
#include <cuda_runtime.h>
#include <cuda_fp16.h>
#include <mma.h>
#include <cstdint>

using namespace nvcuda;

// ============================================================================
// Problem dims (fixed by setup_inputs)
// ============================================================================
#define B_SZ    2
#define S_LEN   2048
#define D_DIM   2048
#define H_DIM   2048
#define F_DIM   6144
#define KCONV   4
#define TOKENS  (B_SZ * S_LEN)   // 4096

#define TD ((size_t)TOKENS * D_DIM)      // 8,388,608
#define TF ((size_t)TOKENS * F_DIM)      // 25,165,824
#define WH_HALVES ((size_t)5 * D_DIM * H_DIM + 3 * (size_t)D_DIM * F_DIM)
#define NCH 16
#define CHL (S_LEN / NCH)                 // 128
#define BNH ((size_t)B_SZ * NCH * H_DIM)  // 65536
// fp32: x1 (TD) + Asum/Bsum/init (3*BNH)
// fp16 (float units): 8 TD-sized half buffers + f1gh + weights
#define SCRATCH_FLOATS (TD + 3 * BNH + (8 * TD + TF + WH_HALVES + 1) / 2 + 64)
__device__ float g_scratch[SCRATCH_FLOATS];

// ============================================================================
// common helpers
// ============================================================================
__device__ __forceinline__ void cp_async16(uint32_t sdst, const void* gsrc) {
    asm volatile("cp.async.cg.shared.global [%0], [%1], 16;"
                 :: "r"(sdst), "l"(gsrc) : "memory");
}
__device__ __forceinline__ void cp_commit() {
    asm volatile("cp.async.commit_group;" ::: "memory");
}
template <int N>
__device__ __forceinline__ void cp_wait() {
    asm volatile("cp.async.wait_group %0;" :: "n"(N) : "memory");
}
__device__ __forceinline__ float gelu_f(float x) {
    return 0.5f * x * (1.0f + erff(x * 0.70710678118654752440f));
}
__device__ __forceinline__ float sigmoid_f(float x) {
    return 1.0f / (1.0f + expf(-x));
}

// ============================================================================
// Single-output fp16 GEMM (dual-B scatter by Nsplit), fused epilogue.
// Tile 128x128x64, 256 threads, 3-stage cp.async. 2 CTAs/SM.
// OUTH: write fp16 outputs (no residual); else fp32 (+optional residual).
// ============================================================================
#define BM 128
#define BN 128
#define BK 64
#define STAGES 3
#define LDA_S 72
#define LDB_S 136
#define LDC_S 132
#define A_ST (BM * LDA_S)                     // 9216 halves
#define B_ST (BK * LDB_S)                     // 8704 halves
#define STAGE_HALVES (A_ST + B_ST)            // 17920
#define PIPE_BYTES (STAGES * STAGE_HALVES * 2)   // 107,520
#define EPI_BYTES (BM * LDC_S * 4)               // 67,584
#define GEMM_SMEM (PIPE_BYTES > EPI_BYTES ? PIPE_BYTES : EPI_BYTES)

// ACT: 0 none, 1 gelu
template <int ACT0, int ACT1, bool RES, bool OUTH>
__global__ void __launch_bounds__(256, 2)
gemm_h_kernel(const __half* __restrict__ A,
              const __half* __restrict__ B0, const __half* __restrict__ B1,
              void* __restrict__ C0, int ldc0, const float* __restrict__ bias0,
              void* __restrict__ C1, int ldc1, const float* __restrict__ bias1,
              const float* __restrict__ res,
              int M, int K, int Nsplit, int ldb0, int ldb1) {
    extern __shared__ __half smemh[];
    const int tid = threadIdx.x;
    const int warp = tid >> 5;
    const int bm = blockIdx.y * BM;
    const int bn = blockIdx.x * BN;

    const bool half1 = (bn >= Nsplit);
    const __half* Bsel = half1 ? B1 : B0;
    const int ldb = half1 ? ldb1 : ldb0;
    const int cb = bn - (half1 ? Nsplit : 0);

    const int wm = (warp >> 1) * 32;
    const int wn = (warp & 1) * 64;

    wmma::fragment<wmma::accumulator, 16, 16, 16, float> acc[2][4];
    #pragma unroll
    for (int mi = 0; mi < 2; mi++)
        #pragma unroll
        for (int ni = 0; ni < 4; ni++)
            wmma::fill_fragment(acc[mi][ni], 0.0f);

    const uint32_t smem_u32 = (uint32_t)__cvta_generic_to_shared(smemh);
    const int nk = K / BK;
    const __half* Abase = A + (size_t)bm * K;
    const __half* Bbase = Bsel + cb;

    auto issue_stage = [&](int s, int kc) {
        const uint32_t sA = smem_u32 + (uint32_t)(s * STAGE_HALVES) * 2u;
        const uint32_t sB = sA + (uint32_t)A_ST * 2u;
        const __half* Ab = Abase + (size_t)kc * BK;
        const __half* Bb = Bbase + (size_t)kc * BK * ldb;
        #pragma unroll
        for (int p = 0; p < 4; p++) {       // A: 128 rows x 8 chunks(8h)
            int id = p * 256 + tid;
            int r = id >> 3, c = id & 7;
            cp_async16(sA + (uint32_t)(r * LDA_S + c * 8) * 2u,
                       Ab + (size_t)r * K + c * 8);
        }
        #pragma unroll
        for (int p = 0; p < 4; p++) {       // B: 64 rows x 16 chunks
            int id = p * 256 + tid;
            int r = id >> 4, c = id & 15;
            cp_async16(sB + (uint32_t)(r * LDB_S + c * 8) * 2u,
                       Bb + (size_t)r * ldb + c * 8);
        }
    };

    #pragma unroll
    for (int s = 0; s < STAGES - 1; s++) { issue_stage(s, s); cp_commit(); }

    int cur = 0;
    for (int kc = 0; kc < nk; kc++) {
        cp_wait<STAGES - 2>();
        __syncthreads();
        int pf = kc + STAGES - 1;
        if (pf < nk) {
            int s = cur + STAGES - 1;
            if (s >= STAGES) s -= STAGES;
            issue_stage(s, pf);
        }
        cp_commit();

        const __half* sA = smemh + cur * STAGE_HALVES;
        const __half* sB = sA + A_ST;
        #pragma unroll
        for (int kk = 0; kk < BK; kk += 16) {
            wmma::fragment<wmma::matrix_b, 16, 16, 16, __half,
                           wmma::row_major> bf[4];
            #pragma unroll
            for (int ni = 0; ni < 4; ni++)
                wmma::load_matrix_sync(bf[ni], sB + kk * LDB_S + wn + ni * 16,
                                       LDB_S);
            #pragma unroll
            for (int mi = 0; mi < 2; mi++) {
                wmma::fragment<wmma::matrix_a, 16, 16, 16, __half,
                               wmma::row_major> af;
                wmma::load_matrix_sync(af, sA + (wm + mi * 16) * LDA_S + kk,
                                       LDA_S);
                #pragma unroll
                for (int ni = 0; ni < 4; ni++)
                    wmma::mma_sync(acc[mi][ni], af, bf[ni], acc[mi][ni]);
            }
        }
        cur = (cur + 1 == STAGES) ? 0 : cur + 1;
    }

    cp_wait<0>();
    __syncthreads();
    float* Cs = reinterpret_cast<float*>(smemh);
    #pragma unroll
    for (int mi = 0; mi < 2; mi++)
        #pragma unroll
        for (int ni = 0; ni < 4; ni++)
            wmma::store_matrix_sync(Cs + (wm + mi * 16) * LDC_S + wn + ni * 16,
                                    acc[mi][ni], LDC_S, wmma::mem_row_major);
    __syncthreads();

    void* Cout = half1 ? C1 : C0;
    const int ldc = half1 ? ldc1 : ldc0;
    const float* bias = half1 ? bias1 : bias0;
    const int act = half1 ? ACT1 : ACT0;

    const int r = tid >> 1;
    const int cseg = (tid & 1) * 64;
    const size_t grow = (size_t)(bm + r);
    const float* biasp = bias + cb + cseg;
    const float* resp = RES ? (res + grow * ldc0 + cb + cseg) : nullptr;
    const float* csrow = Cs + r * LDC_S + cseg;

    #pragma unroll
    for (int j = 0; j < 16; j++) {
        float4 v = *(const float4*)(csrow + j * 4);
        float4 b = *(const float4*)(biasp + j * 4);
        v.x += b.x; v.y += b.y; v.z += b.z; v.w += b.w;
        if (act == 1) {
            v.x = gelu_f(v.x); v.y = gelu_f(v.y);
            v.z = gelu_f(v.z); v.w = gelu_f(v.w);
        }
        if (OUTH) {
            __half* gout = (__half*)Cout + grow * ldc + cb + cseg;
            __half2* dst = (__half2*)(gout + j * 4);
            dst[0] = __floats2half2_rn(v.x, v.y);
            dst[1] = __floats2half2_rn(v.z, v.w);
        } else {
            if (RES) {
                float4 rv = *(const float4*)(resp + j * 4);
                v.x += rv.x; v.y += rv.y; v.z += rv.z; v.w += rv.w;
            }
            float* gout = (float*)Cout + grow * ldc + cb + cseg;
            *(float4*)(gout + j * 4) = v;
        }
    }
}

// ============================================================================
// Dual-accumulator GEMM (same N cols of A@B0 and A@B1, combined epilogue).
// Tile 128 x 64(x2) x 64, 256 threads, 3-stage cp.async. All outputs fp16.
// COMBINE 0 (GLU): out0h = half( gelu(v0+b0) * (v1+b1) )
// COMBINE 1 (AB):  out0h = a = exp(-8*softplus(ap)*sig(v0+b0));
//                  out1h = b = sqrt(-expm1(2la))*sig(v1+b1)*xc  (xc fp16)
// ============================================================================
#define BND 64
#define LDBD 72
#define B_STD (BK * LDBD)                       // 4608 halves
#define STAGE_D (A_ST + 2 * B_STD)              // 18432 halves
#define PIPE_D_BYTES (STAGES * STAGE_D * 2)     // 110,592
#define LDC_D 68
#define EPI_D_BYTES (2 * BM * LDC_D * 4)        // 69,632
#define GEMM_D_SMEM (PIPE_D_BYTES > EPI_D_BYTES ? PIPE_D_BYTES : EPI_D_BYTES)

template <int COMBINE>
__global__ void __launch_bounds__(256, 2)
gemm_dual_kernel(const __half* __restrict__ A,
                 const __half* __restrict__ B0, const __half* __restrict__ B1,
                 __half* __restrict__ out0h, __half* __restrict__ out1h,
                 const float* __restrict__ bias0,
                 const float* __restrict__ bias1,
                 const __half* __restrict__ xch, const float* __restrict__ ap,
                 int M, int N, int K, int ldb) {
    extern __shared__ __half smemh[];
    const int tid = threadIdx.x;
    const int warp = tid >> 5;
    const int bm = blockIdx.y * BM;
    const int bn = blockIdx.x * BND;

    const int wm = (warp >> 1) * 32;
    const int wn = (warp & 1) * 32;

    wmma::fragment<wmma::accumulator, 16, 16, 16, float> acc0[2][2], acc1[2][2];
    #pragma unroll
    for (int mi = 0; mi < 2; mi++)
        #pragma unroll
        for (int ni = 0; ni < 2; ni++) {
            wmma::fill_fragment(acc0[mi][ni], 0.0f);
            wmma::fill_fragment(acc1[mi][ni], 0.0f);
        }

    const uint32_t smem_u32 = (uint32_t)__cvta_generic_to_shared(smemh);
    const int nk = K / BK;
    const __half* Abase = A + (size_t)bm * K;
    const __half* B0base = B0 + bn;
    const __half* B1base = B1 + bn;

    auto issue_stage = [&](int s, int kc) {
        const uint32_t sA = smem_u32 + (uint32_t)(s * STAGE_D) * 2u;
        const uint32_t sB0 = sA + (uint32_t)A_ST * 2u;
        const uint32_t sB1 = sB0 + (uint32_t)B_STD * 2u;
        const __half* Ab = Abase + (size_t)kc * BK;
        const size_t brow = (size_t)kc * BK * ldb;
        #pragma unroll
        for (int p = 0; p < 4; p++) {       // A: 128 rows x 8 chunks
            int id = p * 256 + tid;
            int r = id >> 3, c = id & 7;
            cp_async16(sA + (uint32_t)(r * LDA_S + c * 8) * 2u,
                       Ab + (size_t)r * K + c * 8);
        }
        #pragma unroll
        for (int p = 0; p < 2; p++) {       // B0,B1: 64 rows x 8 chunks each
            int id = p * 256 + tid;
            int r = id >> 3, c = id & 7;
            cp_async16(sB0 + (uint32_t)(r * LDBD + c * 8) * 2u,
                       B0base + brow + (size_t)r * ldb + c * 8);
            cp_async16(sB1 + (uint32_t)(r * LDBD + c * 8) * 2u,
                       B1base + brow + (size_t)r * ldb + c * 8);
        }
    };

    #pragma unroll
    for (int s = 0; s < STAGES - 1; s++) { issue_stage(s, s); cp_commit(); }

    int cur = 0;
    for (int kc = 0; kc < nk; kc++) {
        cp_wait<STAGES - 2>();
        __syncthreads();
        int pf = kc + STAGES - 1;
        if (pf < nk) {
            int s = cur + STAGES - 1;
            if (s >= STAGES) s -= STAGES;
            issue_stage(s, pf);
        }
        cp_commit();

        const __half* sA = smemh + cur * STAGE_D;
        const __half* sB0 = sA + A_ST;
        const __half* sB1 = sB0 + B_STD;
        #pragma unroll
        for (int kk = 0; kk < BK; kk += 16) {
            wmma::fragment<wmma::matrix_b, 16, 16, 16, __half,
                           wmma::row_major> b0f[2], b1f[2];
            #pragma unroll
            for (int ni = 0; ni < 2; ni++) {
                wmma::load_matrix_sync(b0f[ni], sB0 + kk * LDBD + wn + ni * 16,
                                       LDBD);
                wmma::load_matrix_sync(b1f[ni], sB1 + kk * LDBD + wn + ni * 16,
                                       LDBD);
            }
            #pragma unroll
            for (int mi = 0; mi < 2; mi++) {
                wmma::fragment<wmma::matrix_a, 16, 16, 16, __half,
                               wmma::row_major> af;
                wmma::load_matrix_sync(af, sA + (wm + mi * 16) * LDA_S + kk,
                                       LDA_S);
                #pragma unroll
                for (int ni = 0; ni < 2; ni++) {
                    wmma::mma_sync(acc0[mi][ni], af, b0f[ni], acc0[mi][ni]);
                    wmma::mma_sync(acc1[mi][ni], af, b1f[ni], acc1[mi][ni]);
                }
            }
        }
        cur = (cur + 1 == STAGES) ? 0 : cur + 1;
    }

    cp_wait<0>();
    __syncthreads();
    float* Cs0 = reinterpret_cast<float*>(smemh);
    float* Cs1 = Cs0 + BM * LDC_D;
    #pragma unroll
    for (int mi = 0; mi < 2; mi++)
        #pragma unroll
        for (int ni = 0; ni < 2; ni++) {
            wmma::store_matrix_sync(Cs0 + (wm + mi * 16) * LDC_D + wn + ni * 16,
                                    acc0[mi][ni], LDC_D, wmma::mem_row_major);
            wmma::store_matrix_sync(Cs1 + (wm + mi * 16) * LDC_D + wn + ni * 16,
                                    acc1[mi][ni], LDC_D, wmma::mem_row_major);
        }
    __syncthreads();

    const int r = tid >> 1;
    const int c0 = (tid & 1) * 32;
    const size_t row = (size_t)(bm + r);
    const int gcol = bn + c0;

    #pragma unroll
    for (int j = 0; j < 8; j++) {
        const int cc = c0 + j * 4;
        float4 v0 = *(const float4*)(Cs0 + r * LDC_D + cc);
        float4 v1 = *(const float4*)(Cs1 + r * LDC_D + cc);
        float4 b0 = *(const float4*)(bias0 + gcol + j * 4);
        float4 b1 = *(const float4*)(bias1 + gcol + j * 4);
        v0.x += b0.x; v0.y += b0.y; v0.z += b0.z; v0.w += b0.w;
        v1.x += b1.x; v1.y += b1.y; v1.z += b1.z; v1.w += b1.w;
        if (COMBINE == 0) {
            float4 p;
            p.x = gelu_f(v0.x) * v1.x;
            p.y = gelu_f(v0.y) * v1.y;
            p.z = gelu_f(v0.z) * v1.z;
            p.w = gelu_f(v0.w) * v1.w;
            __half2* dst = (__half2*)(out0h + row * N + gcol + j * 4);
            dst[0] = __floats2half2_rn(p.x, p.y);
            dst[1] = __floats2half2_rn(p.z, p.w);
        } else {
            float4 apv = *(const float4*)(ap + gcol + j * 4);
            const __half2* xcp = (const __half2*)(xch + row * N + gcol + j * 4);
            float2 xc01 = __half22float2(xcp[0]);
            float2 xc23 = __half22float2(xcp[1]);
            float av[4], bv[4];
            const float xcv[4] = { xc01.x, xc01.y, xc23.x, xc23.y };
            const float r4[4] = { v0.x, v0.y, v0.z, v0.w };
            const float i4[4] = { v1.x, v1.y, v1.z, v1.w };
            const float ap4[4] = { apv.x, apv.y, apv.z, apv.w };
            #pragma unroll
            for (int q = 0; q < 4; q++) {
                float rr = sigmoid_f(r4[q]), ii = sigmoid_f(i4[q]);
                float la = -8.0f * log1pf(expf(ap4[q])) * rr;
                av[q] = expf(la);
                bv[q] = sqrtf(-expm1f(2.0f * la)) * ii * xcv[q];
            }
            __half2* da = (__half2*)(out0h + row * N + gcol + j * 4);
            da[0] = __floats2half2_rn(av[0], av[1]);
            da[1] = __floats2half2_rn(av[2], av[3]);
            __half2* db = (__half2*)(out1h + row * N + gcol + j * 4);
            db[0] = __floats2half2_rn(bv[0], bv[1]);
            db[1] = __floats2half2_rn(bv[2], bv[3]);
        }
    }
}

// ============================================================================
// Fused fp32->fp16 weight conversion: one launch, 8 segments, vectorized.
// ============================================================================
struct F2HSeg { const float* src; __half* dst; size_t n4; };
struct F2HArgs { F2HSeg seg[8]; };

__global__ void f2h_all_kernel(F2HArgs args) {
    for (int s = 0; s < 8; s++) {
        const float4* src = (const float4*)args.seg[s].src;
        __half2* dst = (__half2*)args.seg[s].dst;
        size_t n4 = args.seg[s].n4;
        for (size_t i = (size_t)blockIdx.x * blockDim.x + threadIdx.x; i < n4;
             i += (size_t)gridDim.x * blockDim.x) {
            float4 v = src[i];
            dst[i * 2 + 0] = __floats2half2_rn(v.x, v.y);
            dst[i * 2 + 1] = __floats2half2_rn(v.z, v.w);
        }
    }
}

// ============================================================================
// RMSNorm: fp32 in, fp16 out, vectorized (float4 / half2).
// One block (256 thr) per row of 2048.
// ============================================================================
__global__ void rmsnorm_h_kernel(const float* __restrict__ x,
                                 const float* __restrict__ w,
                                 __half* __restrict__ out) {
    const int D = D_DIM;
    const float* row = x + (size_t)blockIdx.x * D;
    __half* orow = out + (size_t)blockIdx.x * D;
    const int tid = threadIdx.x;

    float4 v0 = *(const float4*)(row + tid * 8);
    float4 v1 = *(const float4*)(row + tid * 8 + 4);
    float s = v0.x * v0.x + v0.y * v0.y + v0.z * v0.z + v0.w * v0.w
            + v1.x * v1.x + v1.y * v1.y + v1.z * v1.z + v1.w * v1.w;
    #pragma unroll
    for (int off = 16; off > 0; off >>= 1)
        s += __shfl_xor_sync(0xFFFFFFFF, s, off);
    __shared__ float red[8];
    int lane = tid & 31, warp = tid >> 5;
    if (lane == 0) red[warp] = s;
    __syncthreads();
    if (warp == 0) {
        float t = (lane < 8) ? red[lane] : 0.0f;
        #pragma unroll
        for (int off = 4; off > 0; off >>= 1)
            t += __shfl_xor_sync(0xFFFFFFFF, t, off);
        if (lane == 0) red[0] = t;
    }
    __syncthreads();
    float inv = rsqrtf(red[0] / (float)D + 1e-8f);

    float4 w0 = *(const float4*)(w + tid * 8);
    float4 w1 = *(const float4*)(w + tid * 8 + 4);
    __half2* o = (__half2*)(orow + tid * 8);
    o[0] = __floats2half2_rn(w0.x * v0.x * inv, w0.y * v0.y * inv);
    o[1] = __floats2half2_rn(w0.z * v0.z * inv, w0.w * v0.w * inv);
    o[2] = __floats2half2_rn(w1.x * v1.x * inv, w1.y * v1.y * inv);
    o[3] = __floats2half2_rn(w1.z * v1.z * inv, w1.w * v1.w * inv);
}

// ============================================================================
// Causal depthwise conv (K=4): fp16 in, fp16 out, 8 channels per thread.
// ============================================================================
__global__ void conv_h_kernel(const __half* __restrict__ xh,
                              const float* __restrict__ w,
                              const float* __restrict__ bias,
                              __half* __restrict__ yh) {
    const int i = blockIdx.x * blockDim.x + threadIdx.x;   // TOKENS*H/8 threads
    const int h8 = (i & (H_DIM / 8 - 1)) * 8;
    const int tok = i >> 8;                                 // / (H/8=256)
    const int t = tok & (S_LEN - 1);
    const int bb = tok >> 11;

    float acc[8];
    {
        float4 b0 = *(const float4*)(bias + h8);
        float4 b1 = *(const float4*)(bias + h8 + 4);
        acc[0] = b0.x; acc[1] = b0.y; acc[2] = b0.z; acc[3] = b0.w;
        acc[4] = b1.x; acc[5] = b1.y; acc[6] = b1.z; acc[7] = b1.w;
    }
    #pragma unroll
    for (int k = 0; k < KCONV; k++) {
        int tt = t - (KCONV - 1) + k;
        if (tt >= 0) {
            const __half2* xr = (const __half2*)(
                xh + ((size_t)(bb * S_LEN + tt)) * H_DIM + h8);
            float4 w0 = *(const float4*)(w + k * H_DIM + h8);
            float4 w1 = *(const float4*)(w + k * H_DIM + h8 + 4);
            float2 x0 = __half22float2(xr[0]);
            float2 x1 = __half22float2(xr[1]);
            float2 x2 = __half22float2(xr[2]);
            float2 x3 = __half22float2(xr[3]);
            acc[0] = fmaf(w0.x, x0.x, acc[0]);
            acc[1] = fmaf(w0.y, x0.y, acc[1]);
            acc[2] = fmaf(w0.z, x1.x, acc[2]);
            acc[3] = fmaf(w0.w, x1.y, acc[3]);
            acc[4] = fmaf(w1.x, x2.x, acc[4]);
            acc[5] = fmaf(w1.y, x2.y, acc[5]);
            acc[6] = fmaf(w1.z, x3.x, acc[6]);
            acc[7] = fmaf(w1.w, x3.y, acc[7]);
        }
    }
    __half2* o = (__half2*)(yh + (size_t)tok * H_DIM + h8);
    o[0] = __floats2half2_rn(acc[0], acc[1]);
    o[1] = __floats2half2_rn(acc[2], acc[3]);
    o[2] = __floats2half2_rn(acc[4], acc[5]);
    o[3] = __floats2half2_rn(acc[6], acc[7]);
}

// ============================================================================
// Chunked RG-LRU scan, fp16 a/b/left, fp32 state. 2 channels per thread.
// ============================================================================
__global__ void scan_phaseA(const __half* __restrict__ a,
                            const __half* __restrict__ b,
                            float* __restrict__ Asum,
                            float* __restrict__ Bsum) {
    int idx2 = blockIdx.x * blockDim.x + threadIdx.x;   // BNH/2 threads
    int h2 = idx2 & (H_DIM / 2 - 1);
    int c = (idx2 >> 10) & (NCH - 1);
    int bb = idx2 >> 14;
    size_t base2 = (((size_t)(bb * S_LEN + c * CHL)) * H_DIM) / 2 + h2;
    const __half2* a2 = (const __half2*)a;
    const __half2* b2 = (const __half2*)b;
    float2 A = make_float2(1.0f, 1.0f), B = make_float2(0.0f, 0.0f);
    #pragma unroll 4
    for (int t = 0; t < CHL; t++) {
        size_t o = base2 + (size_t)t * (H_DIM / 2);
        float2 av = __half22float2(a2[o]);
        float2 bv = __half22float2(b2[o]);
        B.x = fmaf(av.x, B.x, bv.x);
        B.y = fmaf(av.y, B.y, bv.y);
        A.x *= av.x;
        A.y *= av.y;
    }
    size_t s2 = ((size_t)(bb * NCH + c) * H_DIM) / 2 + h2;
    ((float2*)Asum)[s2] = A;
    ((float2*)Bsum)[s2] = B;
}

__global__ void scan_phaseB(const float* __restrict__ Asum,
                            const float* __restrict__ Bsum,
                            float* __restrict__ init) {
    int idx = blockIdx.x * blockDim.x + threadIdx.x;    // B*H/2 threads
    int h2 = idx & (H_DIM / 2 - 1);
    int bb = idx >> 10;
    float2 state = make_float2(0.0f, 0.0f);
    #pragma unroll
    for (int c = 0; c < NCH; c++) {
        size_t s2 = ((size_t)(bb * NCH + c) * H_DIM) / 2 + h2;
        ((float2*)init)[s2] = state;
        float2 A = ((const float2*)Asum)[s2];
        float2 B = ((const float2*)Bsum)[s2];
        state.x = fmaf(A.x, state.x, B.x);
        state.y = fmaf(A.y, state.y, B.y);
    }
}

__global__ void scan_phaseC(const __half* __restrict__ a,
                            const __half* __restrict__ b,
                            const float* __restrict__ init,
                            const __half* __restrict__ left,
                            __half* __restrict__ lh) {
    int idx2 = blockIdx.x * blockDim.x + threadIdx.x;   // BNH/2 threads
    int h2 = idx2 & (H_DIM / 2 - 1);
    int c = (idx2 >> 10) & (NCH - 1);
    int bb = idx2 >> 14;
    size_t base2 = (((size_t)(bb * S_LEN + c * CHL)) * H_DIM) / 2 + h2;
    size_t s2 = ((size_t)(bb * NCH + c) * H_DIM) / 2 + h2;
    const __half2* a2 = (const __half2*)a;
    const __half2* b2 = (const __half2*)b;
    const __half2* l2 = (const __half2*)left;
    __half2* o2 = (__half2*)lh;
    float2 state = ((const float2*)init)[s2];
    #pragma unroll 4
    for (int t = 0; t < CHL; t++) {
        size_t o = base2 + (size_t)t * (H_DIM / 2);
        float2 av = __half22float2(a2[o]);
        float2 bv = __half22float2(b2[o]);
        float2 lv = __half22float2(l2[o]);
        state.x = fmaf(av.x, state.x, bv.x);
        state.y = fmaf(av.y, state.y, bv.y);
        o2[o] = __floats2half2_rn(lv.x * state.x, lv.y * state.y);
    }
}

// ============================================================================
// Host launch
// ============================================================================
template <int ACT0, int ACT1, bool RES, bool OUTH>
static inline void launch_gemm(const __half* A,
                               const __half* B0, const __half* B1,
                               void* C0, int ldc0, const float* bias0,
                               void* C1, int ldc1, const float* bias1,
                               const float* res,
                               int M, int Ntot, int K, int Nsplit,
                               int ldb0, int ldb1) {
    dim3 grid(Ntot / BN, M / BM);
    gemm_h_kernel<ACT0, ACT1, RES, OUTH><<<grid, 256, GEMM_SMEM>>>(
        A, B0, B1, C0, ldc0, bias0, C1, ldc1, bias1, res,
        M, K, Nsplit, ldb0, ldb1);
}

extern "C" void kernel_launch(void* const* d_in, const int* in_sizes, int n_in,
                              void* d_out, int out_size) {
    (void)in_sizes; (void)n_in; (void)out_size;
    const float* x       = (const float*)d_in[0];
    const float* norm1_w = (const float*)d_in[1];
    const float* left_W  = (const float*)d_in[2];
    const float* left_b  = (const float*)d_in[3];
    const float* right_W = (const float*)d_in[4];
    const float* right_b = (const float*)d_in[5];
    const float* conv_w  = (const float*)d_in[6];
    const float* conv_b  = (const float*)d_in[7];
    const float* ga_W    = (const float*)d_in[8];
    const float* ga_b    = (const float*)d_in[9];
    const float* gx_W    = (const float*)d_in[10];
    const float* gx_b    = (const float*)d_in[11];
    const float* a_param = (const float*)d_in[12];
    const float* out_W   = (const float*)d_in[13];
    const float* out_b   = (const float*)d_in[14];
    const float* norm2_w = (const float*)d_in[15];
    const float* up1_W   = (const float*)d_in[16];
    const float* up1_b   = (const float*)d_in[17];
    const float* up2_W   = (const float*)d_in[18];
    const float* up2_b   = (const float*)d_in[19];
    const float* down_W  = (const float*)d_in[20];
    const float* down_b  = (const float*)d_in[21];
    float* out = (float*)d_out;

    cudaFuncSetAttribute(gemm_h_kernel<1, 0, false, true>,
                         cudaFuncAttributeMaxDynamicSharedMemorySize, GEMM_SMEM);
    cudaFuncSetAttribute(gemm_h_kernel<0, 0, true, false>,
                         cudaFuncAttributeMaxDynamicSharedMemorySize, GEMM_SMEM);
    cudaFuncSetAttribute(gemm_dual_kernel<0>,
                         cudaFuncAttributeMaxDynamicSharedMemorySize, GEMM_D_SMEM);
    cudaFuncSetAttribute(gemm_dual_kernel<1>,
                         cudaFuncAttributeMaxDynamicSharedMemorySize, GEMM_D_SMEM);

    float* scratch = nullptr;
    cudaGetSymbolAddress((void**)&scratch, g_scratch);
    float* x1   = scratch;                       // [TOKENS, D] fp32
    float* Asum = x1 + TD;                       // [BNH]
    float* Bsum = Asum + BNH;
    float* init = Bsum + BNH;
    __half* xnh   = (__half*)(init + BNH);       // [TOKENS, D]
    __half* rph   = xnh + TD;                    // [TOKENS, H] right pre-conv
    __half* cvh   = rph + TD;                    // [TOKENS, H] conv out
    __half* lefth = cvh + TD;                    // [TOKENS, H] gelu(left)
    __half* abh   = lefth + TD;                  // [TOKENS, H] a
    __half* bbh   = abh + TD;                    // [TOKENS, H] b
    __half* lhh   = bbh + TD;                    // [TOKENS, H] left*h
    __half* x1nh  = lhh + TD;                    // [TOKENS, D]
    __half* f1gh  = x1nh + TD;                   // [TOKENS, F]
    __half* wh    = f1gh + TF;
    __half* leftWh  = wh;
    __half* rightWh = leftWh  + (size_t)D_DIM * H_DIM;
    __half* gaWh    = rightWh + (size_t)D_DIM * H_DIM;
    __half* gxWh    = gaWh    + (size_t)H_DIM * H_DIM;
    __half* outWh   = gxWh    + (size_t)H_DIM * H_DIM;
    __half* up1Wh   = outWh   + (size_t)H_DIM * D_DIM;
    __half* up2Wh   = up1Wh   + (size_t)D_DIM * F_DIM;
    __half* downWh  = up2Wh   + (size_t)D_DIM * F_DIM;

    // ---- fused weight conversion ----
    {
        F2HArgs fa;
        fa.seg[0] = { left_W,  leftWh,  (size_t)D_DIM * H_DIM / 4 };
        fa.seg[1] = { right_W, rightWh, (size_t)D_DIM * H_DIM / 4 };
        fa.seg[2] = { ga_W,    gaWh,    (size_t)H_DIM * H_DIM / 4 };
        fa.seg[3] = { gx_W,    gxWh,    (size_t)H_DIM * H_DIM / 4 };
        fa.seg[4] = { out_W,   outWh,   (size_t)H_DIM * D_DIM / 4 };
        fa.seg[5] = { up1_W,   up1Wh,   (size_t)D_DIM * F_DIM / 4 };
        fa.seg[6] = { up2_W,   up2Wh,   (size_t)D_DIM * F_DIM / 4 };
        fa.seg[7] = { down_W,  downWh,  (size_t)F_DIM * D_DIM / 4 };
        f2h_all_kernel<<<2368, 256>>>(fa);
    }

    // ---- recurrent sub-block ----
    rmsnorm_h_kernel<<<TOKENS, 256>>>(x, norm1_w, xnh);

    // left|right, both fp16 out: left = gelu(.), rp = plain
    launch_gemm<1, 0, false, true>(xnh, leftWh, rightWh,
                                   lefth, H_DIM, left_b,
                                   rph, H_DIM, right_b, nullptr,
                                   TOKENS, 2 * H_DIM, D_DIM, H_DIM,
                                   H_DIM, H_DIM);

    conv_h_kernel<<<TOKENS * H_DIM / 8 / 256, 256>>>(rph, conv_w, conv_b, cvh);

    // ga|gx dual with fused RG-LRU gate math -> abh, bbh (fp16)
    {
        dim3 grid(H_DIM / BND, TOKENS / BM);
        gemm_dual_kernel<1><<<grid, 256, GEMM_D_SMEM>>>(
            cvh, gaWh, gxWh, abh, bbh, ga_b, gx_b,
            cvh, a_param, TOKENS, H_DIM, H_DIM, H_DIM);
    }

    // chunked scan: 3 phases (fp16 in/out, fp32 state)
    {
        const int tA2 = (int)(BNH / 2);           // 32768
        scan_phaseA<<<tA2 / 256, 256>>>(abh, bbh, Asum, Bsum);
        scan_phaseB<<<(B_SZ * H_DIM / 2) / 256, 256>>>(Asum, Bsum, init);
        scan_phaseC<<<tA2 / 256, 256>>>(abh, bbh, init, lefth, lhh);
    }

    launch_gemm<0, 0, true, false>(lhh, outWh, outWh,
                                   x1, D_DIM, out_b, nullptr, 0, nullptr, x,
                                   TOKENS, D_DIM, H_DIM, D_DIM, D_DIM, D_DIM);

    // ---- gated MLP sub-block ----
    rmsnorm_h_kernel<<<TOKENS, 256>>>(x1, norm2_w, x1nh);

    {
        dim3 grid(F_DIM / BND, TOKENS / BM);
        gemm_dual_kernel<0><<<grid, 256, GEMM_D_SMEM>>>(
            x1nh, up1Wh, up2Wh, f1gh, nullptr, up1_b, up2_b,
            nullptr, nullptr, TOKENS, F_DIM, D_DIM, F_DIM);
    }

    launch_gemm<0, 0, true, false>(f1gh, downWh, downWh,
                                   out, D_DIM, down_b, nullptr, 0, nullptr, x1,
                                   TOKENS, D_DIM, F_DIM, D_DIM, D_DIM, D_DIM);
}